// round 14
// baseline (speedup 1.0000x reference)
#include <cuda_runtime.h>
#include <math.h>
#include <stdint.h>

#define BATCH 8192
#define NN 4096
#define LDB 68           // padded stride (floats), float4-aligned
#define EPSF 1e-8f
#define SKIP_TAU 1e-6f
#define TAU2 (SKIP_TAU * SKIP_TAU)

#define K0_BLOCKS 256
#define K0_NB 32
#define K2_BLOCKS 2048   // x4 matrices per block (2 per 128-thread group)
#define RT1_BLOCKS 256
#define SWEEPS_BATCH 7
#define SWEEPS_SMALL 8

// ---------------- device scratch ----------------
__device__ __align__(256) float g_partial_mean[(size_t)RT1_BLOCKS * NN];
__device__ __align__(256) float g_mean[NN];
__device__ __align__(256) float g_s[NN];
__device__ __align__(256) float g_si[NN];
__device__ __align__(256) float g_gsqrt[NN];
__device__ __align__(256) float g_W[NN];
__device__ __align__(256) float g_WT[NN];
__device__ __align__(256) float g_partial_t[(size_t)BATCH * NN];
__device__ __align__(256) float g_tmean[NN];

// ---------------- packed f32x2 helpers ----------------
typedef unsigned long long u64;
__device__ __forceinline__ u64 pk2(float x, float y) {
    u64 r; asm("mov.b64 %0,{%1,%2};" : "=l"(r) : "f"(x), "f"(y)); return r;
}
__device__ __forceinline__ void up2(u64 v, float& x, float& y) {
    asm("mov.b64 {%0,%1},%2;" : "=f"(x), "=f"(y) : "l"(v));
}
__device__ __forceinline__ u64 fma2(u64 a, u64 b, u64 c) {
    u64 d; asm("fma.rn.f32x2 %0,%1,%2,%3;" : "=l"(d) : "l"(a), "l"(b), "l"(c)); return d;
}
__device__ __forceinline__ u64 mul2(u64 a, u64 b) {
    u64 d; asm("mul.rn.f32x2 %0,%1,%2;" : "=l"(d) : "l"(a), "l"(b)); return d;
}
__device__ __forceinline__ void barg(int id) {
    asm volatile("bar.sync %0, 128;" :: "r"(id) : "memory");
}

// ---------------- 256-thread helpers (side kernels) ----------------
__device__ __forceinline__ void load_tile(const float* __restrict__ g, float* __restrict__ s) {
    for (int i = threadIdx.x; i < 1024; i += 256) {
        int r = i >> 4, c4 = (i & 15) << 2;
        *(float4*)&s[r * LDB + c4] = *(const float4*)&g[(r << 6) + c4];
    }
}
__device__ __forceinline__ void store_tile(const float* __restrict__ s, float* __restrict__ g) {
    for (int i = threadIdx.x; i < 1024; i += 256) {
        int r = i >> 4, c4 = (i & 15) << 2;
        *(float4*)&g[(r << 6) + c4] = *(const float4*)&s[r * LDB + c4];
    }
}

__device__ __forceinline__ void mm64_t4(const float* __restrict__ A, const float* __restrict__ B,
                                        float* __restrict__ C, int cstride) {
    const int r0 = (threadIdx.x >> 4) << 2;
    const int c0 = (threadIdx.x & 15) << 2;
    u64 acc[8];
#pragma unroll
    for (int i = 0; i < 8; ++i) acc[i] = 0ull;
#pragma unroll 4
    for (int k = 0; k < 64; ++k) {
        float a0 = A[r0 * LDB + k],       a1 = A[(r0 + 1) * LDB + k];
        float a2 = A[(r0 + 2) * LDB + k], a3 = A[(r0 + 3) * LDB + k];
        ulonglong2 b = *(const ulonglong2*)&B[k * LDB + c0];
        u64 p;
        p = pk2(a0, a0); acc[0] = fma2(p, b.x, acc[0]); acc[1] = fma2(p, b.y, acc[1]);
        p = pk2(a1, a1); acc[2] = fma2(p, b.x, acc[2]); acc[3] = fma2(p, b.y, acc[3]);
        p = pk2(a2, a2); acc[4] = fma2(p, b.x, acc[4]); acc[5] = fma2(p, b.y, acc[5]);
        p = pk2(a3, a3); acc[6] = fma2(p, b.x, acc[6]); acc[7] = fma2(p, b.y, acc[7]);
    }
#pragma unroll
    for (int i = 0; i < 4; ++i)
        *(ulonglong2*)&C[(r0 + i) * cstride + c0] = make_ulonglong2(acc[2 * i], acc[2 * i + 1]);
}

__device__ __forceinline__ void gram_t4(const float* __restrict__ Bs, const float* __restrict__ B,
                                        float* __restrict__ out, int ostride) {
    const int r0 = (threadIdx.x >> 4) << 2;
    const int c0 = (threadIdx.x & 15) << 2;
    u64 acc[8];
#pragma unroll
    for (int i = 0; i < 8; ++i) acc[i] = 0ull;
#pragma unroll 4
    for (int j = 0; j < 64; ++j) {
        float4 u = *(const float4*)&Bs[j * LDB + r0];
        ulonglong2 b = *(const ulonglong2*)&B[j * LDB + c0];
        u64 p;
        p = pk2(u.x, u.x); acc[0] = fma2(p, b.x, acc[0]); acc[1] = fma2(p, b.y, acc[1]);
        p = pk2(u.y, u.y); acc[2] = fma2(p, b.x, acc[2]); acc[3] = fma2(p, b.y, acc[3]);
        p = pk2(u.z, u.z); acc[4] = fma2(p, b.x, acc[4]); acc[5] = fma2(p, b.y, acc[5]);
        p = pk2(u.w, u.w); acc[6] = fma2(p, b.x, acc[6]); acc[7] = fma2(p, b.y, acc[7]);
    }
#pragma unroll
    for (int i = 0; i < 4; ++i)
        *(ulonglong2*)&out[(r0 + i) * ostride + c0] = make_ulonglong2(acc[2 * i], acc[2 * i + 1]);
}

__device__ __forceinline__ float colnrm2(const float* __restrict__ B, int j, int seg, float4 v[4]) {
    const float4* c = (const float4*)(B + j * LDB + (seg << 4));
    v[0] = c[0]; v[1] = c[1]; v[2] = c[2]; v[3] = c[3];
    float n = v[0].x * v[0].x;
    n = fmaf(v[0].y, v[0].y, n); n = fmaf(v[0].z, v[0].z, n); n = fmaf(v[0].w, v[0].w, n);
    n = fmaf(v[1].x, v[1].x, n); n = fmaf(v[1].y, v[1].y, n); n = fmaf(v[1].z, v[1].z, n); n = fmaf(v[1].w, v[1].w, n);
    n = fmaf(v[2].x, v[2].x, n); n = fmaf(v[2].y, v[2].y, n); n = fmaf(v[2].z, v[2].z, n); n = fmaf(v[2].w, v[2].w, n);
    n = fmaf(v[3].x, v[3].x, n); n = fmaf(v[3].y, v[3].y, n); n = fmaf(v[3].z, v[3].z, n); n = fmaf(v[3].w, v[3].w, n);
    n += __shfl_xor_sync(0xffffffffu, n, 1);
    n += __shfl_xor_sync(0xffffffffu, n, 2);
    return n;
}

__device__ __forceinline__ void scale_store(float* __restrict__ D, int j, int seg,
                                            const float4 v[4], float f) {
    float4* d = (float4*)(D + j * LDB + (seg << 4));
    d[0] = make_float4(f * v[0].x, f * v[0].y, f * v[0].z, f * v[0].w);
    d[1] = make_float4(f * v[1].x, f * v[1].y, f * v[1].z, f * v[1].w);
    d[2] = make_float4(f * v[2].x, f * v[2].y, f * v[2].z, f * v[2].w);
    d[3] = make_float4(f * v[3].x, f * v[3].y, f * v[3].z, f * v[3].w);
}

// ---------------- smem rot step (side kernels only) ----------------
__device__ __forceinline__ void rot_step(float* __restrict__ B, float* __restrict__ nbuf,
                                         int p, int q, int o0, int o1, int lt) {
    float* bp = B + p * LDB;
    float* bq = B + q * LDB;
    ulonglong2 P0 = *(ulonglong2*)(bp + o0), P1 = *(ulonglong2*)(bp + o1);
    ulonglong2 Q0 = *(ulonglong2*)(bq + o0), Q1 = *(ulonglong2*)(bq + o1);
    u64 spq = mul2(P0.x, Q0.x);
    spq = fma2(P0.y, Q0.y, spq); spq = fma2(P1.x, Q1.x, spq); spq = fma2(P1.y, Q1.y, spq);
    float a0, a1;
    up2(spq, a0, a1);
    float apq = a0 + a1;
    apq += __shfl_xor_sync(0xffffffffu, apq, 1);
    apq += __shfl_xor_sync(0xffffffffu, apq, 2);
    apq += __shfl_xor_sync(0xffffffffu, apq, 4);
    float app = nbuf[p], aqq = nbuf[q];
    if (apq * apq > TAU2 * app * aqq) {
        float zeta = __fdividef(aqq - app, 2.0f * apq);
        float t = __fdividef(copysignf(1.0f, zeta), fabsf(zeta) + sqrtf(fmaf(zeta, zeta, 1.0f)));
        float c = rsqrtf(fmaf(t, t, 1.0f));
        float s = t * c;
        u64 c2 = pk2(c, c), s2 = pk2(s, s), ns2 = pk2(-s, -s);
        ulonglong2 NP0, NP1, NQ0, NQ1;
        NP0.x = fma2(c2, P0.x, mul2(ns2, Q0.x));
        NP0.y = fma2(c2, P0.y, mul2(ns2, Q0.y));
        NP1.x = fma2(c2, P1.x, mul2(ns2, Q1.x));
        NP1.y = fma2(c2, P1.y, mul2(ns2, Q1.y));
        NQ0.x = fma2(s2, P0.x, mul2(c2, Q0.x));
        NQ0.y = fma2(s2, P0.y, mul2(c2, Q0.y));
        NQ1.x = fma2(s2, P1.x, mul2(c2, Q1.x));
        NQ1.y = fma2(s2, P1.y, mul2(c2, Q1.y));
        *(ulonglong2*)(bp + o0) = NP0; *(ulonglong2*)(bp + o1) = NP1;
        *(ulonglong2*)(bq + o0) = NQ0; *(ulonglong2*)(bq + o1) = NQ1;
        if ((lt & 7) == 0) {
            float d = t * apq;
            nbuf[p] = app - d;
            nbuf[q] = aqq + d;
        }
    }
}

__device__ void jacobi_onesided(float* __restrict__ B, float* __restrict__ nbuf, int sweeps) {
    const int tid = threadIdx.x;
    const int k = tid >> 3;
    const int o0 = (tid & 7) << 2;
    const int o1 = 32 + o0;
    const int jn = tid >> 2, segn = tid & 3;
    for (int sw = 0; sw < sweeps; ++sw) {
        {
            float4 v[4];
            float n = colnrm2(B, jn, segn, v);
            if (segn == 0) nbuf[jn] = n;
        }
        __syncthreads();
        int p = (k == 0) ? 0 : k;
        int q = 63 - k;
        for (int rr = 0; rr < 63; ++rr) {
            rot_step(B, nbuf, p, q, o0, o1, tid);
            if (k) p = (p == 63) ? 1 : p + 1;
            q = (q == 63) ? 1 : q + 1;
            __syncthreads();
        }
    }
}

// ---------------- register pair rotation with always-swap (local pairs) ----------------
__device__ __forceinline__ void rotpair(u64 U[4], u64 V[4], float& nu, float& nv, unsigned omask) {
    u64 d = mul2(U[0], V[0]);
    d = fma2(U[1], V[1], d);
    d = fma2(U[2], V[2], d);
    d = fma2(U[3], V[3], d);
    float a0, a1; up2(d, a0, a1);
    float apq = a0 + a1;
    apq += __shfl_xor_sync(omask, apq, 1);
    apq += __shfl_xor_sync(omask, apq, 2);
    apq += __shfl_xor_sync(omask, apq, 4);
    if (apq * apq > TAU2 * nu * nv) {
        float zeta = __fdividef(nv - nu, 2.0f * apq);
        float t = __fdividef(copysignf(1.0f, zeta), fabsf(zeta) + sqrtf(fmaf(zeta, zeta, 1.0f)));
        float c = rsqrtf(fmaf(t, t, 1.0f));
        float s = t * c;
        u64 c2 = pk2(c, c), s2 = pk2(s, s), ns2 = pk2(-s, -s);
#pragma unroll
        for (int i = 0; i < 4; ++i) {
            u64 vp = fma2(s2, U[i], mul2(c2, V[i]));   // v' = s*u + c*v
            u64 up = fma2(c2, U[i], mul2(ns2, V[i]));  // u' = c*u - s*v
            U[i] = vp; V[i] = up;
        }
        float dd = t * apq;
        float a = nu - dd;
        nu = nv + dd;
        nv = a;
    } else {
#pragma unroll
        for (int i = 0; i < 4; ++i) { u64 tmp = U[i]; U[i] = V[i]; V[i] = tmp; }
        float tn = nu; nu = nv; nv = tn;
    }
}

// ---- cross-pair variants: both octets compute same rotation, keep one side ----
// Pair (a=U-side, b=V-side). keepU: U <- v' = s*u + c*v (U had u, D has v).
__device__ __forceinline__ void rotcross_keepU(u64 U[4], const u64 D[4],
                                               float& nu, float nD, unsigned omask) {
    u64 d = mul2(U[0], D[0]);
    d = fma2(U[1], D[1], d);
    d = fma2(U[2], D[2], d);
    d = fma2(U[3], D[3], d);
    float a0, a1; up2(d, a0, a1);
    float apq = a0 + a1;
    apq += __shfl_xor_sync(omask, apq, 1);
    apq += __shfl_xor_sync(omask, apq, 2);
    apq += __shfl_xor_sync(omask, apq, 4);
    if (apq * apq > TAU2 * nu * nD) {
        float zeta = __fdividef(nD - nu, 2.0f * apq);
        float t = __fdividef(copysignf(1.0f, zeta), fabsf(zeta) + sqrtf(fmaf(zeta, zeta, 1.0f)));
        float c = rsqrtf(fmaf(t, t, 1.0f));
        float s = t * c;
        u64 c2 = pk2(c, c), s2 = pk2(s, s);
#pragma unroll
        for (int i = 0; i < 4; ++i)
            U[i] = fma2(s2, U[i], mul2(c2, D[i]));     // v'
        nu = nD + t * apq;
    } else {
#pragma unroll
        for (int i = 0; i < 4; ++i) U[i] = D[i];
        nu = nD;
    }
}
// keepV: V <- u' = c*u - s*v (E has u, V had v). Dot order MUST match keepU: dot(E,V).
__device__ __forceinline__ void rotcross_keepV(const u64 E[4], u64 V[4],
                                               float nE, float& nv, unsigned omask) {
    u64 d = mul2(E[0], V[0]);
    d = fma2(E[1], V[1], d);
    d = fma2(E[2], V[2], d);
    d = fma2(E[3], V[3], d);
    float a0, a1; up2(d, a0, a1);
    float apq = a0 + a1;
    apq += __shfl_xor_sync(omask, apq, 1);
    apq += __shfl_xor_sync(omask, apq, 2);
    apq += __shfl_xor_sync(omask, apq, 4);
    if (apq * apq > TAU2 * nE * nv) {
        float zeta = __fdividef(nv - nE, 2.0f * apq);
        float t = __fdividef(copysignf(1.0f, zeta), fabsf(zeta) + sqrtf(fmaf(zeta, zeta, 1.0f)));
        float c = rsqrtf(fmaf(t, t, 1.0f));
        float s = t * c;
        u64 c2 = pk2(c, c), ns2 = pk2(-s, -s);
#pragma unroll
        for (int i = 0; i < 4; ++i)
            V[i] = fma2(c2, E[i], mul2(ns2, V[i]));    // u'
        nv = nE - t * apq;
    } else {
#pragma unroll
        for (int i = 0; i < 4; ++i) V[i] = E[i];
        nv = nE;
    }
}

// ---------------- 128-thread in-place matmuls ----------------
__device__ __forceinline__ void mmip_left(const float* __restrict__ A, float* __restrict__ X,
                                          int gt, int bid) {
    const int r0 = (gt >> 3) << 2;
    const int cc = (gt & 7) << 2;
#pragma unroll
    for (int cb = 0; cb < 2; ++cb) {
        const int c0 = (cb << 5) + cc;
        u64 acc[8];
#pragma unroll
        for (int i = 0; i < 8; ++i) acc[i] = 0ull;
#pragma unroll 4
        for (int k = 0; k < 64; ++k) {
            float a0 = A[r0 * LDB + k],       a1 = A[(r0 + 1) * LDB + k];
            float a2 = A[(r0 + 2) * LDB + k], a3 = A[(r0 + 3) * LDB + k];
            ulonglong2 b = *(const ulonglong2*)&X[k * LDB + c0];
            u64 p;
            p = pk2(a0, a0); acc[0] = fma2(p, b.x, acc[0]); acc[1] = fma2(p, b.y, acc[1]);
            p = pk2(a1, a1); acc[2] = fma2(p, b.x, acc[2]); acc[3] = fma2(p, b.y, acc[3]);
            p = pk2(a2, a2); acc[4] = fma2(p, b.x, acc[4]); acc[5] = fma2(p, b.y, acc[5]);
            p = pk2(a3, a3); acc[6] = fma2(p, b.x, acc[6]); acc[7] = fma2(p, b.y, acc[7]);
        }
        barg(bid);
#pragma unroll
        for (int i = 0; i < 4; ++i)
            *(ulonglong2*)&X[(r0 + i) * LDB + c0] = make_ulonglong2(acc[2 * i], acc[2 * i + 1]);
        barg(bid);
    }
}

__device__ __forceinline__ void mmip_right(float* __restrict__ X, const float* __restrict__ B,
                                           int gt, int bid) {
    const int rr = (gt >> 4) << 2;
    const int c0 = (gt & 15) << 2;
#pragma unroll
    for (int rb = 0; rb < 2; ++rb) {
        const int r0 = (rb << 5) + rr;
        u64 acc[8];
#pragma unroll
        for (int i = 0; i < 8; ++i) acc[i] = 0ull;
#pragma unroll 4
        for (int k = 0; k < 64; ++k) {
            float a0 = X[r0 * LDB + k],       a1 = X[(r0 + 1) * LDB + k];
            float a2 = X[(r0 + 2) * LDB + k], a3 = X[(r0 + 3) * LDB + k];
            ulonglong2 b = *(const ulonglong2*)&B[k * LDB + c0];
            u64 p;
            p = pk2(a0, a0); acc[0] = fma2(p, b.x, acc[0]); acc[1] = fma2(p, b.y, acc[1]);
            p = pk2(a1, a1); acc[2] = fma2(p, b.x, acc[2]); acc[3] = fma2(p, b.y, acc[3]);
            p = pk2(a2, a2); acc[4] = fma2(p, b.x, acc[4]); acc[5] = fma2(p, b.y, acc[5]);
            p = pk2(a3, a3); acc[6] = fma2(p, b.x, acc[6]); acc[7] = fma2(p, b.y, acc[7]);
        }
        barg(bid);
#pragma unroll
        for (int i = 0; i < 4; ++i)
            *(ulonglong2*)&X[(r0 + i) * LDB + c0] = make_ulonglong2(acc[2 * i], acc[2 * i + 1]);
        barg(bid);
    }
}

__device__ __forceinline__ void gram_g(const float* __restrict__ B, const float* __restrict__ fb,
                                       float* __restrict__ out, int gt) {
    const int c0 = (gt & 15) << 2;
    const int rbase = (gt >> 4) << 3;
#pragma unroll
    for (int half = 0; half < 2; ++half) {
        const int r0 = rbase + (half << 2);
        u64 acc[8];
#pragma unroll
        for (int i = 0; i < 8; ++i) acc[i] = 0ull;
#pragma unroll 4
        for (int j = 0; j < 64; ++j) {
            float f = fb[j];
            float4 u = *(const float4*)&B[j * LDB + r0];
            ulonglong2 b = *(const ulonglong2*)&B[j * LDB + c0];
            u64 p;
            p = pk2(f * u.x, f * u.x); acc[0] = fma2(p, b.x, acc[0]); acc[1] = fma2(p, b.y, acc[1]);
            p = pk2(f * u.y, f * u.y); acc[2] = fma2(p, b.x, acc[2]); acc[3] = fma2(p, b.y, acc[3]);
            p = pk2(f * u.z, f * u.z); acc[4] = fma2(p, b.x, acc[4]); acc[5] = fma2(p, b.y, acc[5]);
            p = pk2(f * u.w, f * u.w); acc[6] = fma2(p, b.x, acc[6]); acc[7] = fma2(p, b.y, acc[7]);
        }
#pragma unroll
        for (int i = 0; i < 4; ++i)
            *(ulonglong2*)&out[(r0 + i) * 64 + c0] = make_ulonglong2(acc[2 * i], acc[2 * i + 1]);
    }
}

// ---------------- kernel 0: arithmetic mean ----------------
__global__ __launch_bounds__(256) void mean_partial_kernel(const float* __restrict__ x) {
    const int g = blockIdx.x, tid = threadIdx.x;
    float4 acc[4] = {{0,0,0,0},{0,0,0,0},{0,0,0,0},{0,0,0,0}};
    const float4* xb = (const float4*)(x + (size_t)g * K0_NB * NN);
    for (int b = 0; b < K0_NB; ++b) {
#pragma unroll
        for (int i = 0; i < 4; ++i) {
            float4 v = xb[(size_t)b * 1024 + tid + (i << 8)];
            acc[i].x += v.x; acc[i].y += v.y; acc[i].z += v.z; acc[i].w += v.w;
        }
    }
    float4* pm = (float4*)(g_partial_mean + (size_t)g * NN);
#pragma unroll
    for (int i = 0; i < 4; ++i) pm[tid + (i << 8)] = acc[i];
}

__global__ void reduce_mean_kernel() {
    int j = blockIdx.x * 128 + threadIdx.x;
    float acc = 0.f;
    for (int g = 0; g < K0_BLOCKS; ++g) acc += g_partial_mean[(size_t)g * NN + j];
    g_mean[j] = acc * (1.0f / BATCH);
}

// ---------------- kernel 1: eigh(mean)->s,si ; eigh(G)->gsqrt ----------------
__global__ __launch_bounds__(256) void prep_kernel(const float* __restrict__ G) {
    extern __shared__ float sm[];
    float* A    = sm;
    float* Bsc  = A + 4352;
    float* nbuf = Bsc + 4352;
    const int tid = threadIdx.x;
    load_tile(blockIdx.x == 0 ? g_mean : G, A);
    __syncthreads();
    jacobi_onesided(A, nbuf, SWEEPS_SMALL);
    const int j = tid >> 2, seg = tid & 3;
    float4 v[4];
    float n = colnrm2(A, j, seg, v);
    float lam = fmaxf(sqrtf(n), EPSF);
    float inv_n = 1.0f / n;
    scale_store(Bsc, j, seg, v, sqrtf(lam) * inv_n);
    __syncthreads();
    gram_t4(Bsc, A, blockIdx.x == 0 ? g_s : g_gsqrt, 64);
    if (blockIdx.x == 0) {
        __syncthreads();
        scale_store(Bsc, j, seg, v, rsqrtf(lam) * inv_n);
        __syncthreads();
        gram_t4(Bsc, A, g_si, 64);
    }
}

// ---------------- kernel 2: logm via register odd-even Jacobi, 1 barrier/round ----------------
__global__ __launch_bounds__(256, 4) void batch_log_kernel(const float* __restrict__ x) {
    extern __shared__ float sm[];
    float* T0 = sm;                       // si (shared, read-only)
    const int tid = threadIdx.x;
    const int g = tid >> 7;
    const int gt = tid & 127;
    const int bid = g + 1;
    float* T  = sm + 4352 + g * 4352;
    float* fb = sm + 3 * 4352 + g * 64;

    load_tile(g_si, T0);
    __syncthreads();                      // only block-wide barrier

    const int o  = gt >> 3;               // octet 0..15, positions 4o..4o+3
    const int o0 = (gt & 7) << 2;
    const int o1 = 32 + o0;
    const unsigned omask = 0xFFu << ((tid & 31) & ~7u);

    for (int mi = 0; mi < 2; ++mi) {
        const size_t mat = (size_t)blockIdx.x * 4 + g * 2 + mi;
        const float* xb = x + mat * NN;
        for (int i = gt; i < 1024; i += 128) {
            int r = i >> 4, c4 = (i & 15) << 2;
            *(float4*)&T[r * LDB + c4] = *(const float4*)&xb[(r << 6) + c4];
        }
        barg(bid);
        mmip_left(T0, T, gt, bid);        // T = si @ x
        mmip_right(T, T0, gt, bid);       // T = T @ si

        // load 4 columns into registers
        u64 C[4][4];
        float nrm[4];
#pragma unroll
        for (int c = 0; c < 4; ++c) {
            const float* base = T + (4 * o + c) * LDB;
            ulonglong2 t0 = *(const ulonglong2*)(base + o0);
            ulonglong2 t1 = *(const ulonglong2*)(base + o1);
            C[c][0] = t0.x; C[c][1] = t0.y; C[c][2] = t1.x; C[c][3] = t1.y;
        }
        barg(bid);                        // T reads done; exchange area live

        for (int sw = 0; sw < SWEEPS_BATCH; ++sw) {
            // refresh norms (registers only)
#pragma unroll
            for (int c = 0; c < 4; ++c) {
                u64 d = mul2(C[c][0], C[c][0]);
                d = fma2(C[c][1], C[c][1], d);
                d = fma2(C[c][2], C[c][2], d);
                d = fma2(C[c][3], C[c][3], d);
                float a0, a1; up2(d, a0, a1);
                float n = a0 + a1;
                n += __shfl_xor_sync(omask, n, 1);
                n += __shfl_xor_sync(omask, n, 2);
                n += __shfl_xor_sync(omask, n, 4);
                nrm[c] = n;
            }
            for (int r = 0; r < 32; ++r) {
                // parity-selected exchange buffers inside dead tile T
                float* xc = T + ((r & 1) ? 2080 : 0);   // fwd: C0 columns (16*64)
                float* bc = xc + 1024;                  // bwd: C3 columns (16*64)
                float* nA = xc + 2048;                  // 16 norms (C0)
                float* nB = nA + 16;                    // 16 norms (C3)
                // odd step: local pairs
                rotpair(C[0], C[1], nrm[0], nrm[1], omask);
                rotpair(C[2], C[3], nrm[2], nrm[3], omask);
                // publish post-odd boundary columns both ways
                *(ulonglong2*)(xc + (o << 6) + o0) = make_ulonglong2(C[0][0], C[0][1]);
                *(ulonglong2*)(xc + (o << 6) + o1) = make_ulonglong2(C[0][2], C[0][3]);
                *(ulonglong2*)(bc + (o << 6) + o0) = make_ulonglong2(C[3][0], C[3][1]);
                *(ulonglong2*)(bc + (o << 6) + o1) = make_ulonglong2(C[3][2], C[3][3]);
                if ((gt & 7) == 0) { nA[o] = nrm[0]; nB[o] = nrm[3]; }
                // even step internal pair — overlaps barrier wait
                rotpair(C[1], C[2], nrm[1], nrm[2], omask);
                barg(bid);
                // cross pairs, redundant symmetric computation (keep own side)
                if (o < 15) {
                    u64 D[4];
                    ulonglong2 t0 = *(const ulonglong2*)(xc + ((o + 1) << 6) + o0);
                    ulonglong2 t1 = *(const ulonglong2*)(xc + ((o + 1) << 6) + o1);
                    D[0] = t0.x; D[1] = t0.y; D[2] = t1.x; D[3] = t1.y;
                    rotcross_keepU(C[3], D, nrm[3], nA[o + 1], omask);
                }
                if (o > 0) {
                    u64 E[4];
                    ulonglong2 t0 = *(const ulonglong2*)(bc + ((o - 1) << 6) + o0);
                    ulonglong2 t1 = *(const ulonglong2*)(bc + ((o - 1) << 6) + o1);
                    E[0] = t0.x; E[1] = t0.y; E[2] = t1.x; E[3] = t1.y;
                    rotcross_keepV(E, C[0], nB[o - 1], nrm[0], omask);
                }
            }
        }
        barg(bid);                        // last exchange reads done before T overwrite

        // epilogue: exact norms, log factors, store columns back to T
#pragma unroll
        for (int c = 0; c < 4; ++c) {
            u64 d = mul2(C[c][0], C[c][0]);
            d = fma2(C[c][1], C[c][1], d);
            d = fma2(C[c][2], C[c][2], d);
            d = fma2(C[c][3], C[c][3], d);
            float a0, a1; up2(d, a0, a1);
            float n = a0 + a1;
            n += __shfl_xor_sync(omask, n, 1);
            n += __shfl_xor_sync(omask, n, 2);
            n += __shfl_xor_sync(omask, n, 4);
            float* base = T + (4 * o + c) * LDB;
            *(ulonglong2*)(base + o0) = make_ulonglong2(C[c][0], C[c][1]);
            *(ulonglong2*)(base + o1) = make_ulonglong2(C[c][2], C[c][3]);
            if ((gt & 7) == 0) fb[4 * o + c] = logf(fmaxf(sqrtf(n), EPSF)) / n;
        }
        barg(bid);
        gram_g(T, fb, g_partial_t + mat * NN, gt);
        barg(bid);
    }
}

// ---------------- reduce_t: two-stage vectorized ----------------
__global__ __launch_bounds__(256) void reduce_t1_kernel() {
    const int g = blockIdx.x, tid = threadIdx.x;
    float4 acc[4] = {{0,0,0,0},{0,0,0,0},{0,0,0,0},{0,0,0,0}};
    const float4* src = (const float4*)(g_partial_t + (size_t)g * 32 * NN);
    for (int b = 0; b < 32; ++b) {
#pragma unroll
        for (int i = 0; i < 4; ++i) {
            float4 v = src[(size_t)b * 1024 + tid + (i << 8)];
            acc[i].x += v.x; acc[i].y += v.y; acc[i].z += v.z; acc[i].w += v.w;
        }
    }
    float4* pm = (float4*)(g_partial_mean + (size_t)g * NN);
#pragma unroll
    for (int i = 0; i < 4; ++i) pm[tid + (i << 8)] = acc[i];
}

__global__ void reduce_t2_kernel() {
    int j = blockIdx.x * 128 + threadIdx.x;
    float acc = 0.f;
    for (int g = 0; g < RT1_BLOCKS; ++g) acc += g_partial_mean[(size_t)g * NN + j];
    g_tmean[j] = acc * (1.0f / BATCH);
}

// ---------------- kernel 3: expm(tmean) via shifted one-sided, center, csi, W, WT ----------------
__global__ __launch_bounds__(256) void center_kernel() {
    extern __shared__ float sm[];
    float* A    = sm;
    float* T1   = A + 4352;
    float* T2   = T1 + 4352;
    float* fw   = T2 + 4352;
    float* nbuf = fw + 64;
    float* sigp = nbuf + 64;
    const int tid = threadIdx.x;
    const int j = tid >> 2, seg = tid & 3;

    load_tile(g_tmean, A);
    __syncthreads();
    {
        const float4* c = (const float4*)(A + j * LDB + (seg << 4));
        float s = 0.f;
#pragma unroll
        for (int i = 0; i < 4; ++i) {
            float4 v = c[i];
            s += fabsf(v.x) + fabsf(v.y) + fabsf(v.z) + fabsf(v.w);
        }
        s += __shfl_xor_sync(0xffffffffu, s, 1);
        s += __shfl_xor_sync(0xffffffffu, s, 2);
        if (seg == 0) fw[j] = s;
    }
    __syncthreads();
    if (tid == 0) {
        float mx = 0.f;
        for (int i = 0; i < 64; ++i) mx = fmaxf(mx, fw[i]);
        sigp[0] = 1.1f * mx + 1e-2f;
    }
    __syncthreads();
    const float sigma = sigp[0];
    if (tid < 64) A[tid * LDB + tid] += sigma;
    __syncthreads();
    jacobi_onesided(A, nbuf, SWEEPS_SMALL);
    {
        float4 v[4];
        float n = colnrm2(A, j, seg, v);
        float mu = fmaxf(sqrtf(n), EPSF);
        float f = expf(mu - sigma) / n;
        scale_store(T1, j, seg, v, f);
    }
    __syncthreads();
    gram_t4(T1, A, T2, LDB);
    __syncthreads();
    load_tile(g_s, A);
    __syncthreads();
    mm64_t4(A, T2, T1, LDB);  __syncthreads();
    mm64_t4(T1, A, T2, LDB);  __syncthreads();
    jacobi_onesided(T2, nbuf, SWEEPS_SMALL);
    {
        float4 v[4];
        float n = colnrm2(T2, j, seg, v);
        float lam = fmaxf(sqrtf(n), EPSF);
        float f = rsqrtf(lam) / n;
        scale_store(T1, j, seg, v, f);
    }
    __syncthreads();
    gram_t4(T1, T2, A, LDB);
    __syncthreads();
    load_tile(g_gsqrt, T1);
    __syncthreads();
    mm64_t4(T1, A, T2, LDB);
    __syncthreads();
    store_tile(T2, g_W);
    for (int idx = tid; idx < NN; idx += 256) {
        int rr = idx >> 6, cc = idx & 63;
        g_WT[(cc << 6) + rr] = T2[rr * LDB + cc];
    }
}

// ---------------- kernel 4: out_b = W x_b W^T ----------------
__global__ __launch_bounds__(256) void output_kernel(const float* __restrict__ x,
                                                     float* __restrict__ out) {
    extern __shared__ float sm[];
    float* Ws = sm;
    float* WT = Ws + 4352;
    float* xs = WT + 4352;
    float* P  = xs + 4352;
    load_tile(g_W, Ws);
    load_tile(g_WT, WT);
    load_tile(x + (size_t)blockIdx.x * NN, xs);
    __syncthreads();
    mm64_t4(Ws, xs, P, LDB);
    __syncthreads();
    mm64_t4(P, WT, out + (size_t)blockIdx.x * NN, 64);
}

// ---------------- launcher ----------------
extern "C" void kernel_launch(void* const* d_in, const int* in_sizes, int n_in,
                              void* d_out, int out_size) {
    const float* x;
    const float* G;
    if (in_sizes[0] == NN) { G = (const float*)d_in[0]; x = (const float*)d_in[1]; }
    else                   { x = (const float*)d_in[0]; G = (const float*)d_in[1]; }
    float* out = (float*)d_out;

    constexpr size_t SM_PREP   = (size_t)(2 * 4352 + 64) * 4;
    constexpr size_t SM_BATCH  = (size_t)(3 * 4352 + 128) * 4;
    constexpr size_t SM_CENTER = (size_t)(3 * 4352 + 64 + 64 + 4) * 4;
    constexpr size_t SM_OUT    = (size_t)(4 * 4352) * 4;

    cudaFuncSetAttribute(batch_log_kernel, cudaFuncAttributeMaxDynamicSharedMemorySize, (int)SM_BATCH);
    cudaFuncSetAttribute(center_kernel,    cudaFuncAttributeMaxDynamicSharedMemorySize, (int)SM_CENTER);
    cudaFuncSetAttribute(output_kernel,    cudaFuncAttributeMaxDynamicSharedMemorySize, (int)SM_OUT);

    mean_partial_kernel<<<K0_BLOCKS, 256>>>(x);
    reduce_mean_kernel<<<32, 128>>>();
    prep_kernel<<<2, 256, SM_PREP>>>(G);
    batch_log_kernel<<<K2_BLOCKS, 256, SM_BATCH>>>(x);
    reduce_t1_kernel<<<RT1_BLOCKS, 256>>>();
    reduce_t2_kernel<<<32, 128>>>();
    center_kernel<<<1, 256, SM_CENTER>>>();
    output_kernel<<<BATCH, 256, SM_OUT>>>(x, out);
}

// round 15
// speedup vs baseline: 1.1368x; 1.1368x over previous
#include <cuda_runtime.h>
#include <math.h>
#include <stdint.h>

#define BATCH 8192
#define NN 4096
#define LDB 68           // padded stride (floats), float4-aligned
#define EPSF 1e-8f
#define SKIP_TAU 1e-6f
#define TAU2 (SKIP_TAU * SKIP_TAU)

#define K0_BLOCKS 256
#define K0_NB 32
#define K2_BLOCKS 2048   // x4 matrices per block (2 per 128-thread group)
#define RT1_BLOCKS 256
#define SWEEPS_BATCH 7
#define SWEEPS_SMALL 8

// ---------------- device scratch ----------------
__device__ __align__(256) float g_partial_mean[(size_t)RT1_BLOCKS * NN];
__device__ __align__(256) float g_mean[NN];
__device__ __align__(256) float g_s[NN];
__device__ __align__(256) float g_si[NN];
__device__ __align__(256) float g_gsqrt[NN];
__device__ __align__(256) float g_W[NN];
__device__ __align__(256) float g_WT[NN];
__device__ __align__(256) float g_partial_t[(size_t)BATCH * NN];
__device__ __align__(256) float g_tmean[NN];

// ---------------- packed f32x2 helpers ----------------
typedef unsigned long long u64;
__device__ __forceinline__ u64 pk2(float x, float y) {
    u64 r; asm("mov.b64 %0,{%1,%2};" : "=l"(r) : "f"(x), "f"(y)); return r;
}
__device__ __forceinline__ void up2(u64 v, float& x, float& y) {
    asm("mov.b64 {%0,%1},%2;" : "=f"(x), "=f"(y) : "l"(v));
}
__device__ __forceinline__ u64 fma2(u64 a, u64 b, u64 c) {
    u64 d; asm("fma.rn.f32x2 %0,%1,%2,%3;" : "=l"(d) : "l"(a), "l"(b), "l"(c)); return d;
}
__device__ __forceinline__ u64 mul2(u64 a, u64 b) {
    u64 d; asm("mul.rn.f32x2 %0,%1,%2;" : "=l"(d) : "l"(a), "l"(b)); return d;
}
__device__ __forceinline__ void barg(int id) {
    asm volatile("bar.sync %0, 128;" :: "r"(id) : "memory");
}

// ---------------- 256-thread helpers (side kernels) ----------------
__device__ __forceinline__ void load_tile(const float* __restrict__ g, float* __restrict__ s) {
    for (int i = threadIdx.x; i < 1024; i += 256) {
        int r = i >> 4, c4 = (i & 15) << 2;
        *(float4*)&s[r * LDB + c4] = *(const float4*)&g[(r << 6) + c4];
    }
}
__device__ __forceinline__ void store_tile(const float* __restrict__ s, float* __restrict__ g) {
    for (int i = threadIdx.x; i < 1024; i += 256) {
        int r = i >> 4, c4 = (i & 15) << 2;
        *(float4*)&g[(r << 6) + c4] = *(const float4*)&s[r * LDB + c4];
    }
}

__device__ __forceinline__ void mm64_t4(const float* __restrict__ A, const float* __restrict__ B,
                                        float* __restrict__ C, int cstride) {
    const int r0 = (threadIdx.x >> 4) << 2;
    const int c0 = (threadIdx.x & 15) << 2;
    u64 acc[8];
#pragma unroll
    for (int i = 0; i < 8; ++i) acc[i] = 0ull;
#pragma unroll 4
    for (int k = 0; k < 64; ++k) {
        float a0 = A[r0 * LDB + k],       a1 = A[(r0 + 1) * LDB + k];
        float a2 = A[(r0 + 2) * LDB + k], a3 = A[(r0 + 3) * LDB + k];
        ulonglong2 b = *(const ulonglong2*)&B[k * LDB + c0];
        u64 p;
        p = pk2(a0, a0); acc[0] = fma2(p, b.x, acc[0]); acc[1] = fma2(p, b.y, acc[1]);
        p = pk2(a1, a1); acc[2] = fma2(p, b.x, acc[2]); acc[3] = fma2(p, b.y, acc[3]);
        p = pk2(a2, a2); acc[4] = fma2(p, b.x, acc[4]); acc[5] = fma2(p, b.y, acc[5]);
        p = pk2(a3, a3); acc[6] = fma2(p, b.x, acc[6]); acc[7] = fma2(p, b.y, acc[7]);
    }
#pragma unroll
    for (int i = 0; i < 4; ++i)
        *(ulonglong2*)&C[(r0 + i) * cstride + c0] = make_ulonglong2(acc[2 * i], acc[2 * i + 1]);
}

__device__ __forceinline__ void gram_t4(const float* __restrict__ Bs, const float* __restrict__ B,
                                        float* __restrict__ out, int ostride) {
    const int r0 = (threadIdx.x >> 4) << 2;
    const int c0 = (threadIdx.x & 15) << 2;
    u64 acc[8];
#pragma unroll
    for (int i = 0; i < 8; ++i) acc[i] = 0ull;
#pragma unroll 4
    for (int j = 0; j < 64; ++j) {
        float4 u = *(const float4*)&Bs[j * LDB + r0];
        ulonglong2 b = *(const ulonglong2*)&B[j * LDB + c0];
        u64 p;
        p = pk2(u.x, u.x); acc[0] = fma2(p, b.x, acc[0]); acc[1] = fma2(p, b.y, acc[1]);
        p = pk2(u.y, u.y); acc[2] = fma2(p, b.x, acc[2]); acc[3] = fma2(p, b.y, acc[3]);
        p = pk2(u.z, u.z); acc[4] = fma2(p, b.x, acc[4]); acc[5] = fma2(p, b.y, acc[5]);
        p = pk2(u.w, u.w); acc[6] = fma2(p, b.x, acc[6]); acc[7] = fma2(p, b.y, acc[7]);
    }
#pragma unroll
    for (int i = 0; i < 4; ++i)
        *(ulonglong2*)&out[(r0 + i) * ostride + c0] = make_ulonglong2(acc[2 * i], acc[2 * i + 1]);
}

__device__ __forceinline__ float colnrm2(const float* __restrict__ B, int j, int seg, float4 v[4]) {
    const float4* c = (const float4*)(B + j * LDB + (seg << 4));
    v[0] = c[0]; v[1] = c[1]; v[2] = c[2]; v[3] = c[3];
    float n = v[0].x * v[0].x;
    n = fmaf(v[0].y, v[0].y, n); n = fmaf(v[0].z, v[0].z, n); n = fmaf(v[0].w, v[0].w, n);
    n = fmaf(v[1].x, v[1].x, n); n = fmaf(v[1].y, v[1].y, n); n = fmaf(v[1].z, v[1].z, n); n = fmaf(v[1].w, v[1].w, n);
    n = fmaf(v[2].x, v[2].x, n); n = fmaf(v[2].y, v[2].y, n); n = fmaf(v[2].z, v[2].z, n); n = fmaf(v[2].w, v[2].w, n);
    n = fmaf(v[3].x, v[3].x, n); n = fmaf(v[3].y, v[3].y, n); n = fmaf(v[3].z, v[3].z, n); n = fmaf(v[3].w, v[3].w, n);
    n += __shfl_xor_sync(0xffffffffu, n, 1);
    n += __shfl_xor_sync(0xffffffffu, n, 2);
    return n;
}

__device__ __forceinline__ void scale_store(float* __restrict__ D, int j, int seg,
                                            const float4 v[4], float f) {
    float4* d = (float4*)(D + j * LDB + (seg << 4));
    d[0] = make_float4(f * v[0].x, f * v[0].y, f * v[0].z, f * v[0].w);
    d[1] = make_float4(f * v[1].x, f * v[1].y, f * v[1].z, f * v[1].w);
    d[2] = make_float4(f * v[2].x, f * v[2].y, f * v[2].z, f * v[2].w);
    d[3] = make_float4(f * v[3].x, f * v[3].y, f * v[3].z, f * v[3].w);
}

// ---------------- smem rot step (side kernels only) ----------------
__device__ __forceinline__ void rot_step(float* __restrict__ B, float* __restrict__ nbuf,
                                         int p, int q, int o0, int o1, int lt) {
    float* bp = B + p * LDB;
    float* bq = B + q * LDB;
    ulonglong2 P0 = *(ulonglong2*)(bp + o0), P1 = *(ulonglong2*)(bp + o1);
    ulonglong2 Q0 = *(ulonglong2*)(bq + o0), Q1 = *(ulonglong2*)(bq + o1);
    u64 spq = mul2(P0.x, Q0.x);
    spq = fma2(P0.y, Q0.y, spq); spq = fma2(P1.x, Q1.x, spq); spq = fma2(P1.y, Q1.y, spq);
    float a0, a1;
    up2(spq, a0, a1);
    float apq = a0 + a1;
    apq += __shfl_xor_sync(0xffffffffu, apq, 1);
    apq += __shfl_xor_sync(0xffffffffu, apq, 2);
    apq += __shfl_xor_sync(0xffffffffu, apq, 4);
    float app = nbuf[p], aqq = nbuf[q];
    if (apq * apq > TAU2 * app * aqq) {
        float zeta = __fdividef(aqq - app, 2.0f * apq);
        float t = __fdividef(copysignf(1.0f, zeta), fabsf(zeta) + sqrtf(fmaf(zeta, zeta, 1.0f)));
        float c = rsqrtf(fmaf(t, t, 1.0f));
        float s = t * c;
        u64 c2 = pk2(c, c), s2 = pk2(s, s), ns2 = pk2(-s, -s);
        ulonglong2 NP0, NP1, NQ0, NQ1;
        NP0.x = fma2(c2, P0.x, mul2(ns2, Q0.x));
        NP0.y = fma2(c2, P0.y, mul2(ns2, Q0.y));
        NP1.x = fma2(c2, P1.x, mul2(ns2, Q1.x));
        NP1.y = fma2(c2, P1.y, mul2(ns2, Q1.y));
        NQ0.x = fma2(s2, P0.x, mul2(c2, Q0.x));
        NQ0.y = fma2(s2, P0.y, mul2(c2, Q0.y));
        NQ1.x = fma2(s2, P1.x, mul2(c2, Q1.x));
        NQ1.y = fma2(s2, P1.y, mul2(c2, Q1.y));
        *(ulonglong2*)(bp + o0) = NP0; *(ulonglong2*)(bp + o1) = NP1;
        *(ulonglong2*)(bq + o0) = NQ0; *(ulonglong2*)(bq + o1) = NQ1;
        if ((lt & 7) == 0) {
            float d = t * apq;
            nbuf[p] = app - d;
            nbuf[q] = aqq + d;
        }
    }
}

__device__ void jacobi_onesided(float* __restrict__ B, float* __restrict__ nbuf, int sweeps) {
    const int tid = threadIdx.x;
    const int k = tid >> 3;
    const int o0 = (tid & 7) << 2;
    const int o1 = 32 + o0;
    const int jn = tid >> 2, segn = tid & 3;
    for (int sw = 0; sw < sweeps; ++sw) {
        {
            float4 v[4];
            float n = colnrm2(B, jn, segn, v);
            if (segn == 0) nbuf[jn] = n;
        }
        __syncthreads();
        int p = (k == 0) ? 0 : k;
        int q = 63 - k;
        for (int rr = 0; rr < 63; ++rr) {
            rot_step(B, nbuf, p, q, o0, o1, tid);
            if (k) p = (p == 63) ? 1 : p + 1;
            q = (q == 63) ? 1 : q + 1;
            __syncthreads();
        }
    }
}

// ---------------- register pair rotation with always-swap ----------------
// U holds position a, V holds position b (a<b). After: U <- v' (rot), V <- u'.
__device__ __forceinline__ void rotpair(u64 U[4], u64 V[4], float& nu, float& nv, unsigned omask) {
    u64 d = mul2(U[0], V[0]);
    d = fma2(U[1], V[1], d);
    d = fma2(U[2], V[2], d);
    d = fma2(U[3], V[3], d);
    float a0, a1; up2(d, a0, a1);
    float apq = a0 + a1;
    apq += __shfl_xor_sync(omask, apq, 1);
    apq += __shfl_xor_sync(omask, apq, 2);
    apq += __shfl_xor_sync(omask, apq, 4);
    if (apq * apq > TAU2 * nu * nv) {
        float zeta = __fdividef(nv - nu, 2.0f * apq);
        float t = __fdividef(copysignf(1.0f, zeta), fabsf(zeta) + sqrtf(fmaf(zeta, zeta, 1.0f)));
        float c = rsqrtf(fmaf(t, t, 1.0f));
        float s = t * c;
        u64 c2 = pk2(c, c), s2 = pk2(s, s), ns2 = pk2(-s, -s);
#pragma unroll
        for (int i = 0; i < 4; ++i) {
            u64 vp = fma2(s2, U[i], mul2(c2, V[i]));   // v' = s*u + c*v
            u64 up = fma2(c2, U[i], mul2(ns2, V[i]));  // u' = c*u - s*v
            U[i] = vp; V[i] = up;
        }
        float dd = t * apq;
        float a = nu - dd;   // norm of u'
        nu = nv + dd;        // U holds v'
        nv = a;
    } else {
#pragma unroll
        for (int i = 0; i < 4; ++i) { u64 tmp = U[i]; U[i] = V[i]; V[i] = tmp; }
        float tn = nu; nu = nv; nv = tn;
    }
}

// ---------------- 128-thread in-place matmuls ----------------
__device__ __forceinline__ void mmip_left(const float* __restrict__ A, float* __restrict__ X,
                                          int gt, int bid) {
    const int r0 = (gt >> 3) << 2;
    const int cc = (gt & 7) << 2;
#pragma unroll
    for (int cb = 0; cb < 2; ++cb) {
        const int c0 = (cb << 5) + cc;
        u64 acc[8];
#pragma unroll
        for (int i = 0; i < 8; ++i) acc[i] = 0ull;
#pragma unroll 4
        for (int k = 0; k < 64; ++k) {
            float a0 = A[r0 * LDB + k],       a1 = A[(r0 + 1) * LDB + k];
            float a2 = A[(r0 + 2) * LDB + k], a3 = A[(r0 + 3) * LDB + k];
            ulonglong2 b = *(const ulonglong2*)&X[k * LDB + c0];
            u64 p;
            p = pk2(a0, a0); acc[0] = fma2(p, b.x, acc[0]); acc[1] = fma2(p, b.y, acc[1]);
            p = pk2(a1, a1); acc[2] = fma2(p, b.x, acc[2]); acc[3] = fma2(p, b.y, acc[3]);
            p = pk2(a2, a2); acc[4] = fma2(p, b.x, acc[4]); acc[5] = fma2(p, b.y, acc[5]);
            p = pk2(a3, a3); acc[6] = fma2(p, b.x, acc[6]); acc[7] = fma2(p, b.y, acc[7]);
        }
        barg(bid);
#pragma unroll
        for (int i = 0; i < 4; ++i)
            *(ulonglong2*)&X[(r0 + i) * LDB + c0] = make_ulonglong2(acc[2 * i], acc[2 * i + 1]);
        barg(bid);
    }
}

__device__ __forceinline__ void mmip_right(float* __restrict__ X, const float* __restrict__ B,
                                           int gt, int bid) {
    const int rr = (gt >> 4) << 2;
    const int c0 = (gt & 15) << 2;
#pragma unroll
    for (int rb = 0; rb < 2; ++rb) {
        const int r0 = (rb << 5) + rr;
        u64 acc[8];
#pragma unroll
        for (int i = 0; i < 8; ++i) acc[i] = 0ull;
#pragma unroll 4
        for (int k = 0; k < 64; ++k) {
            float a0 = X[r0 * LDB + k],       a1 = X[(r0 + 1) * LDB + k];
            float a2 = X[(r0 + 2) * LDB + k], a3 = X[(r0 + 3) * LDB + k];
            ulonglong2 b = *(const ulonglong2*)&B[k * LDB + c0];
            u64 p;
            p = pk2(a0, a0); acc[0] = fma2(p, b.x, acc[0]); acc[1] = fma2(p, b.y, acc[1]);
            p = pk2(a1, a1); acc[2] = fma2(p, b.x, acc[2]); acc[3] = fma2(p, b.y, acc[3]);
            p = pk2(a2, a2); acc[4] = fma2(p, b.x, acc[4]); acc[5] = fma2(p, b.y, acc[5]);
            p = pk2(a3, a3); acc[6] = fma2(p, b.x, acc[6]); acc[7] = fma2(p, b.y, acc[7]);
        }
        barg(bid);
#pragma unroll
        for (int i = 0; i < 4; ++i)
            *(ulonglong2*)&X[(r0 + i) * LDB + c0] = make_ulonglong2(acc[2 * i], acc[2 * i + 1]);
        barg(bid);
    }
}

__device__ __forceinline__ void gram_g(const float* __restrict__ B, const float* __restrict__ fb,
                                       float* __restrict__ out, int gt) {
    const int c0 = (gt & 15) << 2;
    const int rbase = (gt >> 4) << 3;
#pragma unroll
    for (int half = 0; half < 2; ++half) {
        const int r0 = rbase + (half << 2);
        u64 acc[8];
#pragma unroll
        for (int i = 0; i < 8; ++i) acc[i] = 0ull;
#pragma unroll 4
        for (int j = 0; j < 64; ++j) {
            float f = fb[j];
            float4 u = *(const float4*)&B[j * LDB + r0];
            ulonglong2 b = *(const ulonglong2*)&B[j * LDB + c0];
            u64 p;
            p = pk2(f * u.x, f * u.x); acc[0] = fma2(p, b.x, acc[0]); acc[1] = fma2(p, b.y, acc[1]);
            p = pk2(f * u.y, f * u.y); acc[2] = fma2(p, b.x, acc[2]); acc[3] = fma2(p, b.y, acc[3]);
            p = pk2(f * u.z, f * u.z); acc[4] = fma2(p, b.x, acc[4]); acc[5] = fma2(p, b.y, acc[5]);
            p = pk2(f * u.w, f * u.w); acc[6] = fma2(p, b.x, acc[6]); acc[7] = fma2(p, b.y, acc[7]);
        }
#pragma unroll
        for (int i = 0; i < 4; ++i)
            *(ulonglong2*)&out[(r0 + i) * 64 + c0] = make_ulonglong2(acc[2 * i], acc[2 * i + 1]);
    }
}

// ---------------- kernel 0: arithmetic mean ----------------
__global__ __launch_bounds__(256) void mean_partial_kernel(const float* __restrict__ x) {
    const int g = blockIdx.x, tid = threadIdx.x;
    float4 acc[4] = {{0,0,0,0},{0,0,0,0},{0,0,0,0},{0,0,0,0}};
    const float4* xb = (const float4*)(x + (size_t)g * K0_NB * NN);
    for (int b = 0; b < K0_NB; ++b) {
#pragma unroll
        for (int i = 0; i < 4; ++i) {
            float4 v = xb[(size_t)b * 1024 + tid + (i << 8)];
            acc[i].x += v.x; acc[i].y += v.y; acc[i].z += v.z; acc[i].w += v.w;
        }
    }
    float4* pm = (float4*)(g_partial_mean + (size_t)g * NN);
#pragma unroll
    for (int i = 0; i < 4; ++i) pm[tid + (i << 8)] = acc[i];
}

__global__ void reduce_mean_kernel() {
    int j = blockIdx.x * 128 + threadIdx.x;
    float acc = 0.f;
    for (int g = 0; g < K0_BLOCKS; ++g) acc += g_partial_mean[(size_t)g * NN + j];
    g_mean[j] = acc * (1.0f / BATCH);
}

// ---------------- kernel 1: eigh(mean)->s,si ; eigh(G)->gsqrt ----------------
__global__ __launch_bounds__(256) void prep_kernel(const float* __restrict__ G) {
    extern __shared__ float sm[];
    float* A    = sm;
    float* Bsc  = A + 4352;
    float* nbuf = Bsc + 4352;
    const int tid = threadIdx.x;
    load_tile(blockIdx.x == 0 ? g_mean : G, A);
    __syncthreads();
    jacobi_onesided(A, nbuf, SWEEPS_SMALL);
    const int j = tid >> 2, seg = tid & 3;
    float4 v[4];
    float n = colnrm2(A, j, seg, v);
    float lam = fmaxf(sqrtf(n), EPSF);
    float inv_n = 1.0f / n;
    scale_store(Bsc, j, seg, v, sqrtf(lam) * inv_n);
    __syncthreads();
    gram_t4(Bsc, A, blockIdx.x == 0 ? g_s : g_gsqrt, 64);
    if (blockIdx.x == 0) {
        __syncthreads();
        scale_store(Bsc, j, seg, v, rsqrtf(lam) * inv_n);
        __syncthreads();
        gram_t4(Bsc, A, g_si, 64);
    }
}

// ---------------- kernel 2: logm via register-resident odd-even Jacobi ----------------
__global__ __launch_bounds__(256, 3) void batch_log_kernel(const float* __restrict__ x) {
    extern __shared__ float sm[];
    float* T0 = sm;                       // si (shared, read-only)
    const int tid = threadIdx.x;
    const int g = tid >> 7;
    const int gt = tid & 127;
    const int bid = g + 1;
    float* T  = sm + 4352 + g * 4352;
    float* fb = sm + 3 * 4352 + g * 64;

    load_tile(g_si, T0);
    __syncthreads();                      // only block-wide barrier

    const int o  = gt >> 3;               // octet 0..15, positions 4o..4o+3
    const int o0 = (gt & 7) << 2;
    const int o1 = 32 + o0;
    const unsigned omask = 0xFFu << ((tid & 31) & ~7u);
    // exchange buffers inside T (dead during Jacobi)
    float* xcol = T;                      // 16 * 68
    float* ycol = T + 1088;               // 16 * 68
    float* xn   = T + 2176;               // 16
    float* yn   = T + 2192;               // 16

    for (int mi = 0; mi < 2; ++mi) {
        const size_t mat = (size_t)blockIdx.x * 4 + g * 2 + mi;
        const float* xb = x + mat * NN;
        for (int i = gt; i < 1024; i += 128) {
            int r = i >> 4, c4 = (i & 15) << 2;
            *(float4*)&T[r * LDB + c4] = *(const float4*)&xb[(r << 6) + c4];
        }
        barg(bid);
        mmip_left(T0, T, gt, bid);        // T = si @ x
        mmip_right(T, T0, gt, bid);       // T = T @ si

        // load 4 columns into registers
        u64 C[4][4];
        float nrm[4];
#pragma unroll
        for (int c = 0; c < 4; ++c) {
            const float* base = T + (4 * o + c) * LDB;
            ulonglong2 t0 = *(const ulonglong2*)(base + o0);
            ulonglong2 t1 = *(const ulonglong2*)(base + o1);
            C[c][0] = t0.x; C[c][1] = t0.y; C[c][2] = t1.x; C[c][3] = t1.y;
        }
        barg(bid);                        // T reads done; exchange area live

        for (int sw = 0; sw < SWEEPS_BATCH; ++sw) {
            // refresh norms (registers only)
#pragma unroll
            for (int c = 0; c < 4; ++c) {
                u64 d = mul2(C[c][0], C[c][0]);
                d = fma2(C[c][1], C[c][1], d);
                d = fma2(C[c][2], C[c][2], d);
                d = fma2(C[c][3], C[c][3], d);
                float a0, a1; up2(d, a0, a1);
                float n = a0 + a1;
                n += __shfl_xor_sync(omask, n, 1);
                n += __shfl_xor_sync(omask, n, 2);
                n += __shfl_xor_sync(omask, n, 4);
                nrm[c] = n;
            }
            for (int r = 0; r < 32; ++r) {
                // odd round: local pairs (C0,C1), (C2,C3)
                rotpair(C[0], C[1], nrm[0], nrm[1], omask);
                rotpair(C[2], C[3], nrm[2], nrm[3], omask);
                // publish C0 for left neighbor's cross pair
                *(ulonglong2*)(xcol + o * 68 + o0) = make_ulonglong2(C[0][0], C[0][1]);
                *(ulonglong2*)(xcol + o * 68 + o1) = make_ulonglong2(C[0][2], C[0][3]);
                if ((gt & 7) == 0) xn[o] = nrm[0];
                // even round internal pair (C1,C2) — overlap with exchange
                rotpair(C[1], C[2], nrm[1], nrm[2], omask);
                barg(bid);
                if (o < 15) {             // cross pair (C3, neighbor C0)
                    u64 D[4];
                    ulonglong2 t0 = *(const ulonglong2*)(xcol + (o + 1) * 68 + o0);
                    ulonglong2 t1 = *(const ulonglong2*)(xcol + (o + 1) * 68 + o1);
                    D[0] = t0.x; D[1] = t0.y; D[2] = t1.x; D[3] = t1.y;
                    float nD = xn[o + 1];
                    rotpair(C[3], D, nrm[3], nD, omask);
                    *(ulonglong2*)(ycol + (o + 1) * 68 + o0) = make_ulonglong2(D[0], D[1]);
                    *(ulonglong2*)(ycol + (o + 1) * 68 + o1) = make_ulonglong2(D[2], D[3]);
                    if ((gt & 7) == 0) yn[o + 1] = nD;
                }
                barg(bid);
                if (o > 0) {              // receive new C0 (position 4o)
                    ulonglong2 t0 = *(const ulonglong2*)(ycol + o * 68 + o0);
                    ulonglong2 t1 = *(const ulonglong2*)(ycol + o * 68 + o1);
                    C[0][0] = t0.x; C[0][1] = t0.y; C[0][2] = t1.x; C[0][3] = t1.y;
                    nrm[0] = yn[o];
                }
            }
        }
        barg(bid);                        // exchange reads done before T overwrite

        // epilogue: exact norms, log factors, store columns back to T
#pragma unroll
        for (int c = 0; c < 4; ++c) {
            u64 d = mul2(C[c][0], C[c][0]);
            d = fma2(C[c][1], C[c][1], d);
            d = fma2(C[c][2], C[c][2], d);
            d = fma2(C[c][3], C[c][3], d);
            float a0, a1; up2(d, a0, a1);
            float n = a0 + a1;
            n += __shfl_xor_sync(omask, n, 1);
            n += __shfl_xor_sync(omask, n, 2);
            n += __shfl_xor_sync(omask, n, 4);
            float* base = T + (4 * o + c) * LDB;
            *(ulonglong2*)(base + o0) = make_ulonglong2(C[c][0], C[c][1]);
            *(ulonglong2*)(base + o1) = make_ulonglong2(C[c][2], C[c][3]);
            if ((gt & 7) == 0) fb[4 * o + c] = logf(fmaxf(sqrtf(n), EPSF)) / n;
        }
        barg(bid);
        gram_g(T, fb, g_partial_t + mat * NN, gt);
        barg(bid);
    }
}

// ---------------- reduce_t: two-stage vectorized ----------------
__global__ __launch_bounds__(256) void reduce_t1_kernel() {
    const int g = blockIdx.x, tid = threadIdx.x;
    float4 acc[4] = {{0,0,0,0},{0,0,0,0},{0,0,0,0},{0,0,0,0}};
    const float4* src = (const float4*)(g_partial_t + (size_t)g * 32 * NN);
    for (int b = 0; b < 32; ++b) {
#pragma unroll
        for (int i = 0; i < 4; ++i) {
            float4 v = src[(size_t)b * 1024 + tid + (i << 8)];
            acc[i].x += v.x; acc[i].y += v.y; acc[i].z += v.z; acc[i].w += v.w;
        }
    }
    float4* pm = (float4*)(g_partial_mean + (size_t)g * NN);
#pragma unroll
    for (int i = 0; i < 4; ++i) pm[tid + (i << 8)] = acc[i];
}

__global__ void reduce_t2_kernel() {
    int j = blockIdx.x * 128 + threadIdx.x;
    float acc = 0.f;
    for (int g = 0; g < RT1_BLOCKS; ++g) acc += g_partial_mean[(size_t)g * NN + j];
    g_tmean[j] = acc * (1.0f / BATCH);
}

// ---------------- kernel 3: expm(tmean) via shifted one-sided, center, csi, W, WT ----------------
__global__ __launch_bounds__(256) void center_kernel() {
    extern __shared__ float sm[];
    float* A    = sm;
    float* T1   = A + 4352;
    float* T2   = T1 + 4352;
    float* fw   = T2 + 4352;
    float* nbuf = fw + 64;
    float* sigp = nbuf + 64;
    const int tid = threadIdx.x;
    const int j = tid >> 2, seg = tid & 3;

    load_tile(g_tmean, A);
    __syncthreads();
    {
        const float4* c = (const float4*)(A + j * LDB + (seg << 4));
        float s = 0.f;
#pragma unroll
        for (int i = 0; i < 4; ++i) {
            float4 v = c[i];
            s += fabsf(v.x) + fabsf(v.y) + fabsf(v.z) + fabsf(v.w);
        }
        s += __shfl_xor_sync(0xffffffffu, s, 1);
        s += __shfl_xor_sync(0xffffffffu, s, 2);
        if (seg == 0) fw[j] = s;
    }
    __syncthreads();
    if (tid == 0) {
        float mx = 0.f;
        for (int i = 0; i < 64; ++i) mx = fmaxf(mx, fw[i]);
        sigp[0] = 1.1f * mx + 1e-2f;
    }
    __syncthreads();
    const float sigma = sigp[0];
    if (tid < 64) A[tid * LDB + tid] += sigma;
    __syncthreads();
    jacobi_onesided(A, nbuf, SWEEPS_SMALL);
    {
        float4 v[4];
        float n = colnrm2(A, j, seg, v);
        float mu = fmaxf(sqrtf(n), EPSF);
        float f = expf(mu - sigma) / n;
        scale_store(T1, j, seg, v, f);
    }
    __syncthreads();
    gram_t4(T1, A, T2, LDB);
    __syncthreads();
    load_tile(g_s, A);
    __syncthreads();
    mm64_t4(A, T2, T1, LDB);  __syncthreads();
    mm64_t4(T1, A, T2, LDB);  __syncthreads();
    jacobi_onesided(T2, nbuf, SWEEPS_SMALL);
    {
        float4 v[4];
        float n = colnrm2(T2, j, seg, v);
        float lam = fmaxf(sqrtf(n), EPSF);
        float f = rsqrtf(lam) / n;
        scale_store(T1, j, seg, v, f);
    }
    __syncthreads();
    gram_t4(T1, T2, A, LDB);
    __syncthreads();
    load_tile(g_gsqrt, T1);
    __syncthreads();
    mm64_t4(T1, A, T2, LDB);
    __syncthreads();
    store_tile(T2, g_W);
    for (int idx = tid; idx < NN; idx += 256) {
        int rr = idx >> 6, cc = idx & 63;
        g_WT[(cc << 6) + rr] = T2[rr * LDB + cc];
    }
}

// ---------------- kernel 4: out_b = W x_b W^T  (2 matrices per block) ----------------
__global__ __launch_bounds__(256) void output_kernel(const float* __restrict__ x,
                                                     float* __restrict__ out) {
    extern __shared__ float sm[];
    float* Ws = sm;
    float* WT = Ws + 4352;
    float* xs = WT + 4352;
    float* P  = xs + 4352;
    load_tile(g_W, Ws);
    load_tile(g_WT, WT);
#pragma unroll
    for (int m = 0; m < 2; ++m) {
        const size_t b = (size_t)blockIdx.x * 2 + m;
        load_tile(x + b * NN, xs);
        __syncthreads();
        mm64_t4(Ws, xs, P, LDB);
        __syncthreads();
        mm64_t4(P, WT, out + b * NN, 64);
        __syncthreads();
    }
}

// ---------------- launcher ----------------
extern "C" void kernel_launch(void* const* d_in, const int* in_sizes, int n_in,
                              void* d_out, int out_size) {
    const float* x;
    const float* G;
    if (in_sizes[0] == NN) { G = (const float*)d_in[0]; x = (const float*)d_in[1]; }
    else                   { x = (const float*)d_in[0]; G = (const float*)d_in[1]; }
    float* out = (float*)d_out;

    constexpr size_t SM_PREP   = (size_t)(2 * 4352 + 64) * 4;
    constexpr size_t SM_BATCH  = (size_t)(3 * 4352 + 128) * 4;
    constexpr size_t SM_CENTER = (size_t)(3 * 4352 + 64 + 64 + 4) * 4;
    constexpr size_t SM_OUT    = (size_t)(4 * 4352) * 4;

    cudaFuncSetAttribute(batch_log_kernel, cudaFuncAttributeMaxDynamicSharedMemorySize, (int)SM_BATCH);
    cudaFuncSetAttribute(center_kernel,    cudaFuncAttributeMaxDynamicSharedMemorySize, (int)SM_CENTER);
    cudaFuncSetAttribute(output_kernel,    cudaFuncAttributeMaxDynamicSharedMemorySize, (int)SM_OUT);

    mean_partial_kernel<<<K0_BLOCKS, 256>>>(x);
    reduce_mean_kernel<<<32, 128>>>();
    prep_kernel<<<2, 256, SM_PREP>>>(G);
    batch_log_kernel<<<K2_BLOCKS, 256, SM_BATCH>>>(x);
    reduce_t1_kernel<<<RT1_BLOCKS, 256>>>();
    reduce_t2_kernel<<<32, 128>>>();
    center_kernel<<<1, 256, SM_CENTER>>>();
    output_kernel<<<BATCH / 2, 256, SM_OUT>>>(x, out);
}

// round 16
// speedup vs baseline: 1.1569x; 1.0177x over previous
#include <cuda_runtime.h>
#include <math.h>
#include <stdint.h>

#define BATCH 8192
#define NN 4096
#define LDB 68           // padded stride (floats), float4-aligned
#define EPSF 1e-8f
#define SKIP_TAU 1e-6f
#define TAU2 (SKIP_TAU * SKIP_TAU)

#define K0_BLOCKS 256
#define K0_NB 32
#define K2_BLOCKS 2048   // x4 matrices per block (2 per 128-thread group)
#define RT1_BLOCKS 256
#define SWEEPS_BATCH 7
#define SWEEPS_SMALL 8

// ---------------- device scratch ----------------
__device__ __align__(256) float g_partial_mean[(size_t)RT1_BLOCKS * NN];
__device__ __align__(256) float g_mean[NN];
__device__ __align__(256) float g_s[NN];
__device__ __align__(256) float g_si[NN];
__device__ __align__(256) float g_gsqrt[NN];
__device__ __align__(256) float g_W[NN];
__device__ __align__(256) float g_WT[NN];
__device__ __align__(256) float g_partial_t[(size_t)BATCH * NN];
__device__ __align__(256) float g_tmean[NN];

// ---------------- packed f32x2 helpers ----------------
typedef unsigned long long u64;
__device__ __forceinline__ u64 pk2(float x, float y) {
    u64 r; asm("mov.b64 %0,{%1,%2};" : "=l"(r) : "f"(x), "f"(y)); return r;
}
__device__ __forceinline__ void up2(u64 v, float& x, float& y) {
    asm("mov.b64 {%0,%1},%2;" : "=f"(x), "=f"(y) : "l"(v));
}
__device__ __forceinline__ u64 fma2(u64 a, u64 b, u64 c) {
    u64 d; asm("fma.rn.f32x2 %0,%1,%2,%3;" : "=l"(d) : "l"(a), "l"(b), "l"(c)); return d;
}
__device__ __forceinline__ u64 mul2(u64 a, u64 b) {
    u64 d; asm("mul.rn.f32x2 %0,%1,%2;" : "=l"(d) : "l"(a), "l"(b)); return d;
}
__device__ __forceinline__ void barg(int id) {
    asm volatile("bar.sync %0, 128;" :: "r"(id) : "memory");
}

// ---------------- 256-thread helpers (side kernels) ----------------
__device__ __forceinline__ void load_tile(const float* __restrict__ g, float* __restrict__ s) {
    for (int i = threadIdx.x; i < 1024; i += 256) {
        int r = i >> 4, c4 = (i & 15) << 2;
        *(float4*)&s[r * LDB + c4] = *(const float4*)&g[(r << 6) + c4];
    }
}
__device__ __forceinline__ void store_tile(const float* __restrict__ s, float* __restrict__ g) {
    for (int i = threadIdx.x; i < 1024; i += 256) {
        int r = i >> 4, c4 = (i & 15) << 2;
        *(float4*)&g[(r << 6) + c4] = *(const float4*)&s[r * LDB + c4];
    }
}

__device__ __forceinline__ void mm64_t4(const float* __restrict__ A, const float* __restrict__ B,
                                        float* __restrict__ C, int cstride) {
    const int r0 = (threadIdx.x >> 4) << 2;
    const int c0 = (threadIdx.x & 15) << 2;
    u64 acc[8];
#pragma unroll
    for (int i = 0; i < 8; ++i) acc[i] = 0ull;
#pragma unroll 4
    for (int k = 0; k < 64; ++k) {
        float a0 = A[r0 * LDB + k],       a1 = A[(r0 + 1) * LDB + k];
        float a2 = A[(r0 + 2) * LDB + k], a3 = A[(r0 + 3) * LDB + k];
        ulonglong2 b = *(const ulonglong2*)&B[k * LDB + c0];
        u64 p;
        p = pk2(a0, a0); acc[0] = fma2(p, b.x, acc[0]); acc[1] = fma2(p, b.y, acc[1]);
        p = pk2(a1, a1); acc[2] = fma2(p, b.x, acc[2]); acc[3] = fma2(p, b.y, acc[3]);
        p = pk2(a2, a2); acc[4] = fma2(p, b.x, acc[4]); acc[5] = fma2(p, b.y, acc[5]);
        p = pk2(a3, a3); acc[6] = fma2(p, b.x, acc[6]); acc[7] = fma2(p, b.y, acc[7]);
    }
#pragma unroll
    for (int i = 0; i < 4; ++i)
        *(ulonglong2*)&C[(r0 + i) * cstride + c0] = make_ulonglong2(acc[2 * i], acc[2 * i + 1]);
}

__device__ __forceinline__ void gram_t4(const float* __restrict__ Bs, const float* __restrict__ B,
                                        float* __restrict__ out, int ostride) {
    const int r0 = (threadIdx.x >> 4) << 2;
    const int c0 = (threadIdx.x & 15) << 2;
    u64 acc[8];
#pragma unroll
    for (int i = 0; i < 8; ++i) acc[i] = 0ull;
#pragma unroll 4
    for (int j = 0; j < 64; ++j) {
        float4 u = *(const float4*)&Bs[j * LDB + r0];
        ulonglong2 b = *(const ulonglong2*)&B[j * LDB + c0];
        u64 p;
        p = pk2(u.x, u.x); acc[0] = fma2(p, b.x, acc[0]); acc[1] = fma2(p, b.y, acc[1]);
        p = pk2(u.y, u.y); acc[2] = fma2(p, b.x, acc[2]); acc[3] = fma2(p, b.y, acc[3]);
        p = pk2(u.z, u.z); acc[4] = fma2(p, b.x, acc[4]); acc[5] = fma2(p, b.y, acc[5]);
        p = pk2(u.w, u.w); acc[6] = fma2(p, b.x, acc[6]); acc[7] = fma2(p, b.y, acc[7]);
    }
#pragma unroll
    for (int i = 0; i < 4; ++i)
        *(ulonglong2*)&out[(r0 + i) * ostride + c0] = make_ulonglong2(acc[2 * i], acc[2 * i + 1]);
}

__device__ __forceinline__ float colnrm2(const float* __restrict__ B, int j, int seg, float4 v[4]) {
    const float4* c = (const float4*)(B + j * LDB + (seg << 4));
    v[0] = c[0]; v[1] = c[1]; v[2] = c[2]; v[3] = c[3];
    float n = v[0].x * v[0].x;
    n = fmaf(v[0].y, v[0].y, n); n = fmaf(v[0].z, v[0].z, n); n = fmaf(v[0].w, v[0].w, n);
    n = fmaf(v[1].x, v[1].x, n); n = fmaf(v[1].y, v[1].y, n); n = fmaf(v[1].z, v[1].z, n); n = fmaf(v[1].w, v[1].w, n);
    n = fmaf(v[2].x, v[2].x, n); n = fmaf(v[2].y, v[2].y, n); n = fmaf(v[2].z, v[2].z, n); n = fmaf(v[2].w, v[2].w, n);
    n = fmaf(v[3].x, v[3].x, n); n = fmaf(v[3].y, v[3].y, n); n = fmaf(v[3].z, v[3].z, n); n = fmaf(v[3].w, v[3].w, n);
    n += __shfl_xor_sync(0xffffffffu, n, 1);
    n += __shfl_xor_sync(0xffffffffu, n, 2);
    return n;
}

__device__ __forceinline__ void scale_store(float* __restrict__ D, int j, int seg,
                                            const float4 v[4], float f) {
    float4* d = (float4*)(D + j * LDB + (seg << 4));
    d[0] = make_float4(f * v[0].x, f * v[0].y, f * v[0].z, f * v[0].w);
    d[1] = make_float4(f * v[1].x, f * v[1].y, f * v[1].z, f * v[1].w);
    d[2] = make_float4(f * v[2].x, f * v[2].y, f * v[2].z, f * v[2].w);
    d[3] = make_float4(f * v[3].x, f * v[3].y, f * v[3].z, f * v[3].w);
}

// ---------------- smem rot step (side kernels only) ----------------
__device__ __forceinline__ void rot_step(float* __restrict__ B, float* __restrict__ nbuf,
                                         int p, int q, int o0, int o1, int lt) {
    float* bp = B + p * LDB;
    float* bq = B + q * LDB;
    ulonglong2 P0 = *(ulonglong2*)(bp + o0), P1 = *(ulonglong2*)(bp + o1);
    ulonglong2 Q0 = *(ulonglong2*)(bq + o0), Q1 = *(ulonglong2*)(bq + o1);
    u64 spq = mul2(P0.x, Q0.x);
    spq = fma2(P0.y, Q0.y, spq); spq = fma2(P1.x, Q1.x, spq); spq = fma2(P1.y, Q1.y, spq);
    float a0, a1;
    up2(spq, a0, a1);
    float apq = a0 + a1;
    apq += __shfl_xor_sync(0xffffffffu, apq, 1);
    apq += __shfl_xor_sync(0xffffffffu, apq, 2);
    apq += __shfl_xor_sync(0xffffffffu, apq, 4);
    float app = nbuf[p], aqq = nbuf[q];
    if (apq * apq > TAU2 * app * aqq) {
        float zeta = __fdividef(aqq - app, 2.0f * apq);
        float t = __fdividef(copysignf(1.0f, zeta), fabsf(zeta) + sqrtf(fmaf(zeta, zeta, 1.0f)));
        float c = rsqrtf(fmaf(t, t, 1.0f));
        float s = t * c;
        u64 c2 = pk2(c, c), s2 = pk2(s, s), ns2 = pk2(-s, -s);
        ulonglong2 NP0, NP1, NQ0, NQ1;
        NP0.x = fma2(c2, P0.x, mul2(ns2, Q0.x));
        NP0.y = fma2(c2, P0.y, mul2(ns2, Q0.y));
        NP1.x = fma2(c2, P1.x, mul2(ns2, Q1.x));
        NP1.y = fma2(c2, P1.y, mul2(ns2, Q1.y));
        NQ0.x = fma2(s2, P0.x, mul2(c2, Q0.x));
        NQ0.y = fma2(s2, P0.y, mul2(c2, Q0.y));
        NQ1.x = fma2(s2, P1.x, mul2(c2, Q1.x));
        NQ1.y = fma2(s2, P1.y, mul2(c2, Q1.y));
        *(ulonglong2*)(bp + o0) = NP0; *(ulonglong2*)(bp + o1) = NP1;
        *(ulonglong2*)(bq + o0) = NQ0; *(ulonglong2*)(bq + o1) = NQ1;
        if ((lt & 7) == 0) {
            float d = t * apq;
            nbuf[p] = app - d;
            nbuf[q] = aqq + d;
        }
    }
}

__device__ void jacobi_onesided(float* __restrict__ B, float* __restrict__ nbuf, int sweeps) {
    const int tid = threadIdx.x;
    const int k = tid >> 3;
    const int o0 = (tid & 7) << 2;
    const int o1 = 32 + o0;
    const int jn = tid >> 2, segn = tid & 3;
    for (int sw = 0; sw < sweeps; ++sw) {
        {
            float4 v[4];
            float n = colnrm2(B, jn, segn, v);
            if (segn == 0) nbuf[jn] = n;
        }
        __syncthreads();
        int p = (k == 0) ? 0 : k;
        int q = 63 - k;
        for (int rr = 0; rr < 63; ++rr) {
            rot_step(B, nbuf, p, q, o0, o1, tid);
            if (k) p = (p == 63) ? 1 : p + 1;
            q = (q == 63) ? 1 : q + 1;
            __syncthreads();
        }
    }
}

// ---------------- register pair rotation with always-swap ----------------
// U holds position a, V holds position b (a<b). After: U <- v' (rot), V <- u'.
__device__ __forceinline__ void rotpair(u64 U[4], u64 V[4], float& nu, float& nv, unsigned omask) {
    u64 d = mul2(U[0], V[0]);
    d = fma2(U[1], V[1], d);
    d = fma2(U[2], V[2], d);
    d = fma2(U[3], V[3], d);
    float a0, a1; up2(d, a0, a1);
    float apq = a0 + a1;
    apq += __shfl_xor_sync(omask, apq, 1);
    apq += __shfl_xor_sync(omask, apq, 2);
    apq += __shfl_xor_sync(omask, apq, 4);
    if (apq * apq > TAU2 * nu * nv) {
        float zeta = __fdividef(nv - nu, 2.0f * apq);
        float t = __fdividef(copysignf(1.0f, zeta), fabsf(zeta) + sqrtf(fmaf(zeta, zeta, 1.0f)));
        float c = rsqrtf(fmaf(t, t, 1.0f));
        float s = t * c;
        u64 c2 = pk2(c, c), s2 = pk2(s, s), ns2 = pk2(-s, -s);
#pragma unroll
        for (int i = 0; i < 4; ++i) {
            u64 vp = fma2(s2, U[i], mul2(c2, V[i]));   // v' = s*u + c*v
            u64 up = fma2(c2, U[i], mul2(ns2, V[i]));  // u' = c*u - s*v
            U[i] = vp; V[i] = up;
        }
        float dd = t * apq;
        float a = nu - dd;   // norm of u'
        nu = nv + dd;        // U holds v'
        nv = a;
    } else {
#pragma unroll
        for (int i = 0; i < 4; ++i) { u64 tmp = U[i]; U[i] = V[i]; V[i] = tmp; }
        float tn = nu; nu = nv; nv = tn;
    }
}

// ---------------- fused dual-pair rotation: interleaved shuffle trees ----------------
// Bit-identical per-pair arithmetic to two rotpair calls; the two dot products
// and their reduction trees are interleaved so the second tree hides under the
// first tree's SHFL latency.
__device__ __forceinline__ void rotpair2(u64 U0[4], u64 V0[4], float& nu0, float& nv0,
                                         u64 U1[4], u64 V1[4], float& nu1, float& nv1,
                                         unsigned omask) {
    u64 d0 = mul2(U0[0], V0[0]);
    u64 d1 = mul2(U1[0], V1[0]);
    d0 = fma2(U0[1], V0[1], d0);  d1 = fma2(U1[1], V1[1], d1);
    d0 = fma2(U0[2], V0[2], d0);  d1 = fma2(U1[2], V1[2], d1);
    d0 = fma2(U0[3], V0[3], d0);  d1 = fma2(U1[3], V1[3], d1);
    float a, b;
    up2(d0, a, b); float p0 = a + b;
    up2(d1, a, b); float p1 = a + b;
    p0 += __shfl_xor_sync(omask, p0, 1);
    p1 += __shfl_xor_sync(omask, p1, 1);
    p0 += __shfl_xor_sync(omask, p0, 2);
    p1 += __shfl_xor_sync(omask, p1, 2);
    p0 += __shfl_xor_sync(omask, p0, 4);
    p1 += __shfl_xor_sync(omask, p1, 4);
    // pair 0 rotate/swap
    if (p0 * p0 > TAU2 * nu0 * nv0) {
        float zeta = __fdividef(nv0 - nu0, 2.0f * p0);
        float t = __fdividef(copysignf(1.0f, zeta), fabsf(zeta) + sqrtf(fmaf(zeta, zeta, 1.0f)));
        float c = rsqrtf(fmaf(t, t, 1.0f));
        float s = t * c;
        u64 c2 = pk2(c, c), s2 = pk2(s, s), ns2 = pk2(-s, -s);
#pragma unroll
        for (int i = 0; i < 4; ++i) {
            u64 vp = fma2(s2, U0[i], mul2(c2, V0[i]));
            u64 up = fma2(c2, U0[i], mul2(ns2, V0[i]));
            U0[i] = vp; V0[i] = up;
        }
        float dd = t * p0;
        float t2 = nu0 - dd;
        nu0 = nv0 + dd;
        nv0 = t2;
    } else {
#pragma unroll
        for (int i = 0; i < 4; ++i) { u64 tmp = U0[i]; U0[i] = V0[i]; V0[i] = tmp; }
        float tn = nu0; nu0 = nv0; nv0 = tn;
    }
    // pair 1 rotate/swap
    if (p1 * p1 > TAU2 * nu1 * nv1) {
        float zeta = __fdividef(nv1 - nu1, 2.0f * p1);
        float t = __fdividef(copysignf(1.0f, zeta), fabsf(zeta) + sqrtf(fmaf(zeta, zeta, 1.0f)));
        float c = rsqrtf(fmaf(t, t, 1.0f));
        float s = t * c;
        u64 c2 = pk2(c, c), s2 = pk2(s, s), ns2 = pk2(-s, -s);
#pragma unroll
        for (int i = 0; i < 4; ++i) {
            u64 vp = fma2(s2, U1[i], mul2(c2, V1[i]));
            u64 up = fma2(c2, U1[i], mul2(ns2, V1[i]));
            U1[i] = vp; V1[i] = up;
        }
        float dd = t * p1;
        float t2 = nu1 - dd;
        nu1 = nv1 + dd;
        nv1 = t2;
    } else {
#pragma unroll
        for (int i = 0; i < 4; ++i) { u64 tmp = U1[i]; U1[i] = V1[i]; V1[i] = tmp; }
        float tn = nu1; nu1 = nv1; nv1 = tn;
    }
}

// ---------------- 128-thread in-place matmuls ----------------
__device__ __forceinline__ void mmip_left(const float* __restrict__ A, float* __restrict__ X,
                                          int gt, int bid) {
    const int r0 = (gt >> 3) << 2;
    const int cc = (gt & 7) << 2;
#pragma unroll
    for (int cb = 0; cb < 2; ++cb) {
        const int c0 = (cb << 5) + cc;
        u64 acc[8];
#pragma unroll
        for (int i = 0; i < 8; ++i) acc[i] = 0ull;
#pragma unroll 4
        for (int k = 0; k < 64; ++k) {
            float a0 = A[r0 * LDB + k],       a1 = A[(r0 + 1) * LDB + k];
            float a2 = A[(r0 + 2) * LDB + k], a3 = A[(r0 + 3) * LDB + k];
            ulonglong2 b = *(const ulonglong2*)&X[k * LDB + c0];
            u64 p;
            p = pk2(a0, a0); acc[0] = fma2(p, b.x, acc[0]); acc[1] = fma2(p, b.y, acc[1]);
            p = pk2(a1, a1); acc[2] = fma2(p, b.x, acc[2]); acc[3] = fma2(p, b.y, acc[3]);
            p = pk2(a2, a2); acc[4] = fma2(p, b.x, acc[4]); acc[5] = fma2(p, b.y, acc[5]);
            p = pk2(a3, a3); acc[6] = fma2(p, b.x, acc[6]); acc[7] = fma2(p, b.y, acc[7]);
        }
        barg(bid);
#pragma unroll
        for (int i = 0; i < 4; ++i)
            *(ulonglong2*)&X[(r0 + i) * LDB + c0] = make_ulonglong2(acc[2 * i], acc[2 * i + 1]);
        barg(bid);
    }
}

__device__ __forceinline__ void mmip_right(float* __restrict__ X, const float* __restrict__ B,
                                           int gt, int bid) {
    const int rr = (gt >> 4) << 2;
    const int c0 = (gt & 15) << 2;
#pragma unroll
    for (int rb = 0; rb < 2; ++rb) {
        const int r0 = (rb << 5) + rr;
        u64 acc[8];
#pragma unroll
        for (int i = 0; i < 8; ++i) acc[i] = 0ull;
#pragma unroll 4
        for (int k = 0; k < 64; ++k) {
            float a0 = X[r0 * LDB + k],       a1 = X[(r0 + 1) * LDB + k];
            float a2 = X[(r0 + 2) * LDB + k], a3 = X[(r0 + 3) * LDB + k];
            ulonglong2 b = *(const ulonglong2*)&B[k * LDB + c0];
            u64 p;
            p = pk2(a0, a0); acc[0] = fma2(p, b.x, acc[0]); acc[1] = fma2(p, b.y, acc[1]);
            p = pk2(a1, a1); acc[2] = fma2(p, b.x, acc[2]); acc[3] = fma2(p, b.y, acc[3]);
            p = pk2(a2, a2); acc[4] = fma2(p, b.x, acc[4]); acc[5] = fma2(p, b.y, acc[5]);
            p = pk2(a3, a3); acc[6] = fma2(p, b.x, acc[6]); acc[7] = fma2(p, b.y, acc[7]);
        }
        barg(bid);
#pragma unroll
        for (int i = 0; i < 4; ++i)
            *(ulonglong2*)&X[(r0 + i) * LDB + c0] = make_ulonglong2(acc[2 * i], acc[2 * i + 1]);
        barg(bid);
    }
}

__device__ __forceinline__ void gram_g(const float* __restrict__ B, const float* __restrict__ fb,
                                       float* __restrict__ out, int gt) {
    const int c0 = (gt & 15) << 2;
    const int rbase = (gt >> 4) << 3;
#pragma unroll
    for (int half = 0; half < 2; ++half) {
        const int r0 = rbase + (half << 2);
        u64 acc[8];
#pragma unroll
        for (int i = 0; i < 8; ++i) acc[i] = 0ull;
#pragma unroll 4
        for (int j = 0; j < 64; ++j) {
            float f = fb[j];
            float4 u = *(const float4*)&B[j * LDB + r0];
            ulonglong2 b = *(const ulonglong2*)&B[j * LDB + c0];
            u64 p;
            p = pk2(f * u.x, f * u.x); acc[0] = fma2(p, b.x, acc[0]); acc[1] = fma2(p, b.y, acc[1]);
            p = pk2(f * u.y, f * u.y); acc[2] = fma2(p, b.x, acc[2]); acc[3] = fma2(p, b.y, acc[3]);
            p = pk2(f * u.z, f * u.z); acc[4] = fma2(p, b.x, acc[4]); acc[5] = fma2(p, b.y, acc[5]);
            p = pk2(f * u.w, f * u.w); acc[6] = fma2(p, b.x, acc[6]); acc[7] = fma2(p, b.y, acc[7]);
        }
#pragma unroll
        for (int i = 0; i < 4; ++i)
            *(ulonglong2*)&out[(r0 + i) * 64 + c0] = make_ulonglong2(acc[2 * i], acc[2 * i + 1]);
    }
}

// ---------------- kernel 0: arithmetic mean ----------------
__global__ __launch_bounds__(256) void mean_partial_kernel(const float* __restrict__ x) {
    const int g = blockIdx.x, tid = threadIdx.x;
    float4 acc[4] = {{0,0,0,0},{0,0,0,0},{0,0,0,0},{0,0,0,0}};
    const float4* xb = (const float4*)(x + (size_t)g * K0_NB * NN);
    for (int b = 0; b < K0_NB; ++b) {
#pragma unroll
        for (int i = 0; i < 4; ++i) {
            float4 v = xb[(size_t)b * 1024 + tid + (i << 8)];
            acc[i].x += v.x; acc[i].y += v.y; acc[i].z += v.z; acc[i].w += v.w;
        }
    }
    float4* pm = (float4*)(g_partial_mean + (size_t)g * NN);
#pragma unroll
    for (int i = 0; i < 4; ++i) pm[tid + (i << 8)] = acc[i];
}

__global__ void reduce_mean_kernel() {
    int j = blockIdx.x * 128 + threadIdx.x;
    float acc = 0.f;
    for (int g = 0; g < K0_BLOCKS; ++g) acc += g_partial_mean[(size_t)g * NN + j];
    g_mean[j] = acc * (1.0f / BATCH);
}

// ---------------- kernel 1: eigh(mean)->s,si ; eigh(G)->gsqrt ----------------
__global__ __launch_bounds__(256) void prep_kernel(const float* __restrict__ G) {
    extern __shared__ float sm[];
    float* A    = sm;
    float* Bsc  = A + 4352;
    float* nbuf = Bsc + 4352;
    const int tid = threadIdx.x;
    load_tile(blockIdx.x == 0 ? g_mean : G, A);
    __syncthreads();
    jacobi_onesided(A, nbuf, SWEEPS_SMALL);
    const int j = tid >> 2, seg = tid & 3;
    float4 v[4];
    float n = colnrm2(A, j, seg, v);
    float lam = fmaxf(sqrtf(n), EPSF);
    float inv_n = 1.0f / n;
    scale_store(Bsc, j, seg, v, sqrtf(lam) * inv_n);
    __syncthreads();
    gram_t4(Bsc, A, blockIdx.x == 0 ? g_s : g_gsqrt, 64);
    if (blockIdx.x == 0) {
        __syncthreads();
        scale_store(Bsc, j, seg, v, rsqrtf(lam) * inv_n);
        __syncthreads();
        gram_t4(Bsc, A, g_si, 64);
    }
}

// ---------------- kernel 2: logm via register-resident odd-even Jacobi ----------------
__global__ __launch_bounds__(256, 3) void batch_log_kernel(const float* __restrict__ x) {
    extern __shared__ float sm[];
    float* T0 = sm;                       // si (shared, read-only)
    const int tid = threadIdx.x;
    const int g = tid >> 7;
    const int gt = tid & 127;
    const int bid = g + 1;
    float* T  = sm + 4352 + g * 4352;
    float* fb = sm + 3 * 4352 + g * 64;

    load_tile(g_si, T0);
    __syncthreads();                      // only block-wide barrier

    const int o  = gt >> 3;               // octet 0..15, positions 4o..4o+3
    const int o0 = (gt & 7) << 2;
    const int o1 = 32 + o0;
    const unsigned omask = 0xFFu << ((tid & 31) & ~7u);
    // exchange buffers inside T (dead during Jacobi)
    float* xcol = T;                      // 16 * 68
    float* ycol = T + 1088;               // 16 * 68
    float* xn   = T + 2176;               // 16
    float* yn   = T + 2192;               // 16

    for (int mi = 0; mi < 2; ++mi) {
        const size_t mat = (size_t)blockIdx.x * 4 + g * 2 + mi;
        const float* xb = x + mat * NN;
        for (int i = gt; i < 1024; i += 128) {
            int r = i >> 4, c4 = (i & 15) << 2;
            *(float4*)&T[r * LDB + c4] = *(const float4*)&xb[(r << 6) + c4];
        }
        barg(bid);
        mmip_left(T0, T, gt, bid);        // T = si @ x
        mmip_right(T, T0, gt, bid);       // T = T @ si

        // load 4 columns into registers
        u64 C[4][4];
        float nrm[4];
#pragma unroll
        for (int c = 0; c < 4; ++c) {
            const float* base = T + (4 * o + c) * LDB;
            ulonglong2 t0 = *(const ulonglong2*)(base + o0);
            ulonglong2 t1 = *(const ulonglong2*)(base + o1);
            C[c][0] = t0.x; C[c][1] = t0.y; C[c][2] = t1.x; C[c][3] = t1.y;
        }
        barg(bid);                        // T reads done; exchange area live

        for (int sw = 0; sw < SWEEPS_BATCH; ++sw) {
            // refresh norms (registers only)
#pragma unroll
            for (int c = 0; c < 4; ++c) {
                u64 d = mul2(C[c][0], C[c][0]);
                d = fma2(C[c][1], C[c][1], d);
                d = fma2(C[c][2], C[c][2], d);
                d = fma2(C[c][3], C[c][3], d);
                float a0, a1; up2(d, a0, a1);
                float n = a0 + a1;
                n += __shfl_xor_sync(omask, n, 1);
                n += __shfl_xor_sync(omask, n, 2);
                n += __shfl_xor_sync(omask, n, 4);
                nrm[c] = n;
            }
            for (int r = 0; r < 32; ++r) {
                // odd round: local pairs (C0,C1), (C2,C3) fused
                rotpair2(C[0], C[1], nrm[0], nrm[1],
                         C[2], C[3], nrm[2], nrm[3], omask);
                // publish C0 for left neighbor's cross pair
                *(ulonglong2*)(xcol + o * 68 + o0) = make_ulonglong2(C[0][0], C[0][1]);
                *(ulonglong2*)(xcol + o * 68 + o1) = make_ulonglong2(C[0][2], C[0][3]);
                if ((gt & 7) == 0) xn[o] = nrm[0];
                // even round internal pair (C1,C2) — overlap with exchange
                rotpair(C[1], C[2], nrm[1], nrm[2], omask);
                barg(bid);
                if (o < 15) {             // cross pair (C3, neighbor C0)
                    u64 D[4];
                    ulonglong2 t0 = *(const ulonglong2*)(xcol + (o + 1) * 68 + o0);
                    ulonglong2 t1 = *(const ulonglong2*)(xcol + (o + 1) * 68 + o1);
                    D[0] = t0.x; D[1] = t0.y; D[2] = t1.x; D[3] = t1.y;
                    float nD = xn[o + 1];
                    rotpair(C[3], D, nrm[3], nD, omask);
                    *(ulonglong2*)(ycol + (o + 1) * 68 + o0) = make_ulonglong2(D[0], D[1]);
                    *(ulonglong2*)(ycol + (o + 1) * 68 + o1) = make_ulonglong2(D[2], D[3]);
                    if ((gt & 7) == 0) yn[o + 1] = nD;
                }
                barg(bid);
                if (o > 0) {              // receive new C0 (position 4o)
                    ulonglong2 t0 = *(const ulonglong2*)(ycol + o * 68 + o0);
                    ulonglong2 t1 = *(const ulonglong2*)(ycol + o * 68 + o1);
                    C[0][0] = t0.x; C[0][1] = t0.y; C[0][2] = t1.x; C[0][3] = t1.y;
                    nrm[0] = yn[o];
                }
            }
        }
        barg(bid);                        // exchange reads done before T overwrite

        // epilogue: exact norms, log factors, store columns back to T
#pragma unroll
        for (int c = 0; c < 4; ++c) {
            u64 d = mul2(C[c][0], C[c][0]);
            d = fma2(C[c][1], C[c][1], d);
            d = fma2(C[c][2], C[c][2], d);
            d = fma2(C[c][3], C[c][3], d);
            float a0, a1; up2(d, a0, a1);
            float n = a0 + a1;
            n += __shfl_xor_sync(omask, n, 1);
            n += __shfl_xor_sync(omask, n, 2);
            n += __shfl_xor_sync(omask, n, 4);
            float* base = T + (4 * o + c) * LDB;
            *(ulonglong2*)(base + o0) = make_ulonglong2(C[c][0], C[c][1]);
            *(ulonglong2*)(base + o1) = make_ulonglong2(C[c][2], C[c][3]);
            if ((gt & 7) == 0) fb[4 * o + c] = logf(fmaxf(sqrtf(n), EPSF)) / n;
        }
        barg(bid);
        gram_g(T, fb, g_partial_t + mat * NN, gt);
        barg(bid);
    }
}

// ---------------- reduce_t: two-stage vectorized ----------------
__global__ __launch_bounds__(256) void reduce_t1_kernel() {
    const int g = blockIdx.x, tid = threadIdx.x;
    float4 acc[4] = {{0,0,0,0},{0,0,0,0},{0,0,0,0},{0,0,0,0}};
    const float4* src = (const float4*)(g_partial_t + (size_t)g * 32 * NN);
    for (int b = 0; b < 32; ++b) {
#pragma unroll
        for (int i = 0; i < 4; ++i) {
            float4 v = src[(size_t)b * 1024 + tid + (i << 8)];
            acc[i].x += v.x; acc[i].y += v.y; acc[i].z += v.z; acc[i].w += v.w;
        }
    }
    float4* pm = (float4*)(g_partial_mean + (size_t)g * NN);
#pragma unroll
    for (int i = 0; i < 4; ++i) pm[tid + (i << 8)] = acc[i];
}

__global__ void reduce_t2_kernel() {
    int j = blockIdx.x * 128 + threadIdx.x;
    float acc = 0.f;
    for (int g = 0; g < RT1_BLOCKS; ++g) acc += g_partial_mean[(size_t)g * NN + j];
    g_tmean[j] = acc * (1.0f / BATCH);
}

// ---------------- kernel 3: expm(tmean) via shifted one-sided, center, csi, W, WT ----------------
__global__ __launch_bounds__(256) void center_kernel() {
    extern __shared__ float sm[];
    float* A    = sm;
    float* T1   = A + 4352;
    float* T2   = T1 + 4352;
    float* fw   = T2 + 4352;
    float* nbuf = fw + 64;
    float* sigp = nbuf + 64;
    const int tid = threadIdx.x;
    const int j = tid >> 2, seg = tid & 3;

    load_tile(g_tmean, A);
    __syncthreads();
    {
        const float4* c = (const float4*)(A + j * LDB + (seg << 4));
        float s = 0.f;
#pragma unroll
        for (int i = 0; i < 4; ++i) {
            float4 v = c[i];
            s += fabsf(v.x) + fabsf(v.y) + fabsf(v.z) + fabsf(v.w);
        }
        s += __shfl_xor_sync(0xffffffffu, s, 1);
        s += __shfl_xor_sync(0xffffffffu, s, 2);
        if (seg == 0) fw[j] = s;
    }
    __syncthreads();
    if (tid == 0) {
        float mx = 0.f;
        for (int i = 0; i < 64; ++i) mx = fmaxf(mx, fw[i]);
        sigp[0] = 1.1f * mx + 1e-2f;
    }
    __syncthreads();
    const float sigma = sigp[0];
    if (tid < 64) A[tid * LDB + tid] += sigma;
    __syncthreads();
    jacobi_onesided(A, nbuf, SWEEPS_SMALL);
    {
        float4 v[4];
        float n = colnrm2(A, j, seg, v);
        float mu = fmaxf(sqrtf(n), EPSF);
        float f = expf(mu - sigma) / n;
        scale_store(T1, j, seg, v, f);
    }
    __syncthreads();
    gram_t4(T1, A, T2, LDB);
    __syncthreads();
    load_tile(g_s, A);
    __syncthreads();
    mm64_t4(A, T2, T1, LDB);  __syncthreads();
    mm64_t4(T1, A, T2, LDB);  __syncthreads();
    jacobi_onesided(T2, nbuf, SWEEPS_SMALL);
    {
        float4 v[4];
        float n = colnrm2(T2, j, seg, v);
        float lam = fmaxf(sqrtf(n), EPSF);
        float f = rsqrtf(lam) / n;
        scale_store(T1, j, seg, v, f);
    }
    __syncthreads();
    gram_t4(T1, T2, A, LDB);
    __syncthreads();
    load_tile(g_gsqrt, T1);
    __syncthreads();
    mm64_t4(T1, A, T2, LDB);
    __syncthreads();
    store_tile(T2, g_W);
    for (int idx = tid; idx < NN; idx += 256) {
        int rr = idx >> 6, cc = idx & 63;
        g_WT[(cc << 6) + rr] = T2[rr * LDB + cc];
    }
}

// ---------------- kernel 4: out_b = W x_b W^T  (4 matrices per block) ----------------
__global__ __launch_bounds__(256) void output_kernel(const float* __restrict__ x,
                                                     float* __restrict__ out) {
    extern __shared__ float sm[];
    float* Ws = sm;
    float* WT = Ws + 4352;
    float* xs = WT + 4352;
    float* P  = xs + 4352;
    load_tile(g_W, Ws);
    load_tile(g_WT, WT);
#pragma unroll
    for (int m = 0; m < 4; ++m) {
        const size_t b = (size_t)blockIdx.x * 4 + m;
        load_tile(x + b * NN, xs);
        __syncthreads();
        mm64_t4(Ws, xs, P, LDB);
        __syncthreads();
        mm64_t4(P, WT, out + b * NN, 64);
        __syncthreads();
    }
}

// ---------------- launcher ----------------
extern "C" void kernel_launch(void* const* d_in, const int* in_sizes, int n_in,
                              void* d_out, int out_size) {
    const float* x;
    const float* G;
    if (in_sizes[0] == NN) { G = (const float*)d_in[0]; x = (const float*)d_in[1]; }
    else                   { x = (const float*)d_in[0]; G = (const float*)d_in[1]; }
    float* out = (float*)d_out;

    constexpr size_t SM_PREP   = (size_t)(2 * 4352 + 64) * 4;
    constexpr size_t SM_BATCH  = (size_t)(3 * 4352 + 128) * 4;
    constexpr size_t SM_CENTER = (size_t)(3 * 4352 + 64 + 64 + 4) * 4;
    constexpr size_t SM_OUT    = (size_t)(4 * 4352) * 4;

    cudaFuncSetAttribute(batch_log_kernel, cudaFuncAttributeMaxDynamicSharedMemorySize, (int)SM_BATCH);
    cudaFuncSetAttribute(center_kernel,    cudaFuncAttributeMaxDynamicSharedMemorySize, (int)SM_CENTER);
    cudaFuncSetAttribute(output_kernel,    cudaFuncAttributeMaxDynamicSharedMemorySize, (int)SM_OUT);

    mean_partial_kernel<<<K0_BLOCKS, 256>>>(x);
    reduce_mean_kernel<<<32, 128>>>();
    prep_kernel<<<2, 256, SM_PREP>>>(G);
    batch_log_kernel<<<K2_BLOCKS, 256, SM_BATCH>>>(x);
    reduce_t1_kernel<<<RT1_BLOCKS, 256>>>();
    reduce_t2_kernel<<<32, 128>>>();
    center_kernel<<<1, 256, SM_CENTER>>>();
    output_kernel<<<BATCH / 4, 256, SM_OUT>>>(x, out);
}

// round 17
// speedup vs baseline: 1.2632x; 1.0918x over previous
#include <cuda_runtime.h>
#include <math.h>
#include <stdint.h>

#define BATCH 8192
#define NN 4096
#define LDB 68           // padded stride (floats), float4-aligned
#define EPSF 1e-8f
#define SKIP_TAU 1e-6f
#define TAU2 (SKIP_TAU * SKIP_TAU)

#define K0_BLOCKS 256
#define K0_NB 32
#define K2_BLOCKS 2048   // x4 matrices per block (2 per 128-thread group)
#define RT1_BLOCKS 256
#define SWEEPS_BATCH 7
#define SWEEPS_SMALL 8

// ---------------- device scratch ----------------
__device__ __align__(256) float g_partial_mean[(size_t)RT1_BLOCKS * NN];
__device__ __align__(256) float g_mean[NN];
__device__ __align__(256) float g_s[NN];
__device__ __align__(256) float g_si[NN];
__device__ __align__(256) float g_gsqrt[NN];
__device__ __align__(256) float g_W[NN];
__device__ __align__(256) float g_WT[NN];
__device__ __align__(256) float g_partial_t[(size_t)BATCH * NN];
__device__ __align__(256) float g_tmean[NN];

// ---------------- packed f32x2 helpers ----------------
typedef unsigned long long u64;
__device__ __forceinline__ u64 pk2(float x, float y) {
    u64 r; asm("mov.b64 %0,{%1,%2};" : "=l"(r) : "f"(x), "f"(y)); return r;
}
__device__ __forceinline__ void up2(u64 v, float& x, float& y) {
    asm("mov.b64 {%0,%1},%2;" : "=f"(x), "=f"(y) : "l"(v));
}
__device__ __forceinline__ u64 fma2(u64 a, u64 b, u64 c) {
    u64 d; asm("fma.rn.f32x2 %0,%1,%2,%3;" : "=l"(d) : "l"(a), "l"(b), "l"(c)); return d;
}
__device__ __forceinline__ u64 mul2(u64 a, u64 b) {
    u64 d; asm("mul.rn.f32x2 %0,%1,%2;" : "=l"(d) : "l"(a), "l"(b)); return d;
}
__device__ __forceinline__ void barg(int id) {
    asm volatile("bar.sync %0, 128;" :: "r"(id) : "memory");
}

// ---------------- 256-thread helpers (side kernels) ----------------
__device__ __forceinline__ void load_tile(const float* __restrict__ g, float* __restrict__ s) {
    for (int i = threadIdx.x; i < 1024; i += 256) {
        int r = i >> 4, c4 = (i & 15) << 2;
        *(float4*)&s[r * LDB + c4] = *(const float4*)&g[(r << 6) + c4];
    }
}
__device__ __forceinline__ void store_tile(const float* __restrict__ s, float* __restrict__ g) {
    for (int i = threadIdx.x; i < 1024; i += 256) {
        int r = i >> 4, c4 = (i & 15) << 2;
        *(float4*)&g[(r << 6) + c4] = *(const float4*)&s[r * LDB + c4];
    }
}

__device__ __forceinline__ void mm64_t4(const float* __restrict__ A, const float* __restrict__ B,
                                        float* __restrict__ C, int cstride) {
    const int r0 = (threadIdx.x >> 4) << 2;
    const int c0 = (threadIdx.x & 15) << 2;
    u64 acc[8];
#pragma unroll
    for (int i = 0; i < 8; ++i) acc[i] = 0ull;
#pragma unroll 4
    for (int k = 0; k < 64; ++k) {
        float a0 = A[r0 * LDB + k],       a1 = A[(r0 + 1) * LDB + k];
        float a2 = A[(r0 + 2) * LDB + k], a3 = A[(r0 + 3) * LDB + k];
        ulonglong2 b = *(const ulonglong2*)&B[k * LDB + c0];
        u64 p;
        p = pk2(a0, a0); acc[0] = fma2(p, b.x, acc[0]); acc[1] = fma2(p, b.y, acc[1]);
        p = pk2(a1, a1); acc[2] = fma2(p, b.x, acc[2]); acc[3] = fma2(p, b.y, acc[3]);
        p = pk2(a2, a2); acc[4] = fma2(p, b.x, acc[4]); acc[5] = fma2(p, b.y, acc[5]);
        p = pk2(a3, a3); acc[6] = fma2(p, b.x, acc[6]); acc[7] = fma2(p, b.y, acc[7]);
    }
#pragma unroll
    for (int i = 0; i < 4; ++i)
        *(ulonglong2*)&C[(r0 + i) * cstride + c0] = make_ulonglong2(acc[2 * i], acc[2 * i + 1]);
}

__device__ __forceinline__ void gram_t4(const float* __restrict__ Bs, const float* __restrict__ B,
                                        float* __restrict__ out, int ostride) {
    const int r0 = (threadIdx.x >> 4) << 2;
    const int c0 = (threadIdx.x & 15) << 2;
    u64 acc[8];
#pragma unroll
    for (int i = 0; i < 8; ++i) acc[i] = 0ull;
#pragma unroll 4
    for (int j = 0; j < 64; ++j) {
        float4 u = *(const float4*)&Bs[j * LDB + r0];
        ulonglong2 b = *(const ulonglong2*)&B[j * LDB + c0];
        u64 p;
        p = pk2(u.x, u.x); acc[0] = fma2(p, b.x, acc[0]); acc[1] = fma2(p, b.y, acc[1]);
        p = pk2(u.y, u.y); acc[2] = fma2(p, b.x, acc[2]); acc[3] = fma2(p, b.y, acc[3]);
        p = pk2(u.z, u.z); acc[4] = fma2(p, b.x, acc[4]); acc[5] = fma2(p, b.y, acc[5]);
        p = pk2(u.w, u.w); acc[6] = fma2(p, b.x, acc[6]); acc[7] = fma2(p, b.y, acc[7]);
    }
#pragma unroll
    for (int i = 0; i < 4; ++i)
        *(ulonglong2*)&out[(r0 + i) * ostride + c0] = make_ulonglong2(acc[2 * i], acc[2 * i + 1]);
}

__device__ __forceinline__ float colnrm2(const float* __restrict__ B, int j, int seg, float4 v[4]) {
    const float4* c = (const float4*)(B + j * LDB + (seg << 4));
    v[0] = c[0]; v[1] = c[1]; v[2] = c[2]; v[3] = c[3];
    float n = v[0].x * v[0].x;
    n = fmaf(v[0].y, v[0].y, n); n = fmaf(v[0].z, v[0].z, n); n = fmaf(v[0].w, v[0].w, n);
    n = fmaf(v[1].x, v[1].x, n); n = fmaf(v[1].y, v[1].y, n); n = fmaf(v[1].z, v[1].z, n); n = fmaf(v[1].w, v[1].w, n);
    n = fmaf(v[2].x, v[2].x, n); n = fmaf(v[2].y, v[2].y, n); n = fmaf(v[2].z, v[2].z, n); n = fmaf(v[2].w, v[2].w, n);
    n = fmaf(v[3].x, v[3].x, n); n = fmaf(v[3].y, v[3].y, n); n = fmaf(v[3].z, v[3].z, n); n = fmaf(v[3].w, v[3].w, n);
    n += __shfl_xor_sync(0xffffffffu, n, 1);
    n += __shfl_xor_sync(0xffffffffu, n, 2);
    return n;
}

__device__ __forceinline__ void scale_store(float* __restrict__ D, int j, int seg,
                                            const float4 v[4], float f) {
    float4* d = (float4*)(D + j * LDB + (seg << 4));
    d[0] = make_float4(f * v[0].x, f * v[0].y, f * v[0].z, f * v[0].w);
    d[1] = make_float4(f * v[1].x, f * v[1].y, f * v[1].z, f * v[1].w);
    d[2] = make_float4(f * v[2].x, f * v[2].y, f * v[2].z, f * v[2].w);
    d[3] = make_float4(f * v[3].x, f * v[3].y, f * v[3].z, f * v[3].w);
}

// ---------------- smem rot step (side kernels only) ----------------
__device__ __forceinline__ void rot_step(float* __restrict__ B, float* __restrict__ nbuf,
                                         int p, int q, int o0, int o1, int lt) {
    float* bp = B + p * LDB;
    float* bq = B + q * LDB;
    ulonglong2 P0 = *(ulonglong2*)(bp + o0), P1 = *(ulonglong2*)(bp + o1);
    ulonglong2 Q0 = *(ulonglong2*)(bq + o0), Q1 = *(ulonglong2*)(bq + o1);
    u64 spq = mul2(P0.x, Q0.x);
    spq = fma2(P0.y, Q0.y, spq); spq = fma2(P1.x, Q1.x, spq); spq = fma2(P1.y, Q1.y, spq);
    float a0, a1;
    up2(spq, a0, a1);
    float apq = a0 + a1;
    apq += __shfl_xor_sync(0xffffffffu, apq, 1);
    apq += __shfl_xor_sync(0xffffffffu, apq, 2);
    apq += __shfl_xor_sync(0xffffffffu, apq, 4);
    float app = nbuf[p], aqq = nbuf[q];
    if (apq * apq > TAU2 * app * aqq) {
        float zeta = __fdividef(aqq - app, 2.0f * apq);
        float t = __fdividef(copysignf(1.0f, zeta), fabsf(zeta) + sqrtf(fmaf(zeta, zeta, 1.0f)));
        float c = rsqrtf(fmaf(t, t, 1.0f));
        float s = t * c;
        u64 c2 = pk2(c, c), s2 = pk2(s, s), ns2 = pk2(-s, -s);
        ulonglong2 NP0, NP1, NQ0, NQ1;
        NP0.x = fma2(c2, P0.x, mul2(ns2, Q0.x));
        NP0.y = fma2(c2, P0.y, mul2(ns2, Q0.y));
        NP1.x = fma2(c2, P1.x, mul2(ns2, Q1.x));
        NP1.y = fma2(c2, P1.y, mul2(ns2, Q1.y));
        NQ0.x = fma2(s2, P0.x, mul2(c2, Q0.x));
        NQ0.y = fma2(s2, P0.y, mul2(c2, Q0.y));
        NQ1.x = fma2(s2, P1.x, mul2(c2, Q1.x));
        NQ1.y = fma2(s2, P1.y, mul2(c2, Q1.y));
        *(ulonglong2*)(bp + o0) = NP0; *(ulonglong2*)(bp + o1) = NP1;
        *(ulonglong2*)(bq + o0) = NQ0; *(ulonglong2*)(bq + o1) = NQ1;
        if ((lt & 7) == 0) {
            float d = t * apq;
            nbuf[p] = app - d;
            nbuf[q] = aqq + d;
        }
    }
}

__device__ void jacobi_onesided(float* __restrict__ B, float* __restrict__ nbuf, int sweeps) {
    const int tid = threadIdx.x;
    const int k = tid >> 3;
    const int o0 = (tid & 7) << 2;
    const int o1 = 32 + o0;
    const int jn = tid >> 2, segn = tid & 3;
    for (int sw = 0; sw < sweeps; ++sw) {
        {
            float4 v[4];
            float n = colnrm2(B, jn, segn, v);
            if (segn == 0) nbuf[jn] = n;
        }
        __syncthreads();
        int p = (k == 0) ? 0 : k;
        int q = 63 - k;
        for (int rr = 0; rr < 63; ++rr) {
            rot_step(B, nbuf, p, q, o0, o1, tid);
            if (k) p = (p == 63) ? 1 : p + 1;
            q = (q == 63) ? 1 : q + 1;
            __syncthreads();
        }
    }
}

// ---------------- BRANCHLESS register pair rotation with always-swap ----------------
// The skip+swap case is exactly the rotation with (c,s,t)=(1,0,0):
//   U' = 0*U + 1*V = V,  V' = 1*U - 0*V = U,  dd = 0  -> bit-exact swap.
// So the 16-fma rotation block runs unconditionally; only (c,s,t) are selected.
// Removes the warp-divergent branch (4 octets/warp decide independently) and
// all swap MOVs.
__device__ __forceinline__ void rotpair(u64 U[4], u64 V[4], float& nu, float& nv, unsigned omask) {
    u64 d = mul2(U[0], V[0]);
    d = fma2(U[1], V[1], d);
    d = fma2(U[2], V[2], d);
    d = fma2(U[3], V[3], d);
    float a0, a1; up2(d, a0, a1);
    float apq = a0 + a1;
    apq += __shfl_xor_sync(omask, apq, 1);
    apq += __shfl_xor_sync(omask, apq, 2);
    apq += __shfl_xor_sync(omask, apq, 4);
    bool rot = apq * apq > TAU2 * nu * nv;
    float denom = rot ? (2.0f * apq) : 1.0f;
    float zeta = __fdividef(nv - nu, denom);
    float t = __fdividef(copysignf(1.0f, zeta), fabsf(zeta) + sqrtf(fmaf(zeta, zeta, 1.0f)));
    float c = rsqrtf(fmaf(t, t, 1.0f));
    float s = t * c;
    if (!rot) { c = 1.0f; s = 0.0f; t = 0.0f; }
    u64 c2 = pk2(c, c), s2 = pk2(s, s), ns2 = pk2(-s, -s);
#pragma unroll
    for (int i = 0; i < 4; ++i) {
        u64 vp = fma2(s2, U[i], mul2(c2, V[i]));   // v' = s*u + c*v
        u64 up = fma2(c2, U[i], mul2(ns2, V[i]));  // u' = c*u - s*v
        U[i] = vp; V[i] = up;
    }
    float dd = t * apq;
    float a = nu - dd;
    nu = nv + dd;
    nv = a;
}

// ---------------- fused dual-pair rotation (branchless, interleaved trees) ----------------
__device__ __forceinline__ void rotpair2(u64 U0[4], u64 V0[4], float& nu0, float& nv0,
                                         u64 U1[4], u64 V1[4], float& nu1, float& nv1,
                                         unsigned omask) {
    u64 d0 = mul2(U0[0], V0[0]);
    u64 d1 = mul2(U1[0], V1[0]);
    d0 = fma2(U0[1], V0[1], d0);  d1 = fma2(U1[1], V1[1], d1);
    d0 = fma2(U0[2], V0[2], d0);  d1 = fma2(U1[2], V1[2], d1);
    d0 = fma2(U0[3], V0[3], d0);  d1 = fma2(U1[3], V1[3], d1);
    float a, b;
    up2(d0, a, b); float p0 = a + b;
    up2(d1, a, b); float p1 = a + b;
    p0 += __shfl_xor_sync(omask, p0, 1);
    p1 += __shfl_xor_sync(omask, p1, 1);
    p0 += __shfl_xor_sync(omask, p0, 2);
    p1 += __shfl_xor_sync(omask, p1, 2);
    p0 += __shfl_xor_sync(omask, p0, 4);
    p1 += __shfl_xor_sync(omask, p1, 4);
    bool rot0 = p0 * p0 > TAU2 * nu0 * nv0;
    bool rot1 = p1 * p1 > TAU2 * nu1 * nv1;
    float den0 = rot0 ? (2.0f * p0) : 1.0f;
    float den1 = rot1 ? (2.0f * p1) : 1.0f;
    float z0 = __fdividef(nv0 - nu0, den0);
    float z1 = __fdividef(nv1 - nu1, den1);
    float t0 = __fdividef(copysignf(1.0f, z0), fabsf(z0) + sqrtf(fmaf(z0, z0, 1.0f)));
    float t1 = __fdividef(copysignf(1.0f, z1), fabsf(z1) + sqrtf(fmaf(z1, z1, 1.0f)));
    float c0 = rsqrtf(fmaf(t0, t0, 1.0f));
    float c1 = rsqrtf(fmaf(t1, t1, 1.0f));
    float s0 = t0 * c0;
    float s1 = t1 * c1;
    if (!rot0) { c0 = 1.0f; s0 = 0.0f; t0 = 0.0f; }
    if (!rot1) { c1 = 1.0f; s1 = 0.0f; t1 = 0.0f; }
    {
        u64 c2 = pk2(c0, c0), s2 = pk2(s0, s0), ns2 = pk2(-s0, -s0);
#pragma unroll
        for (int i = 0; i < 4; ++i) {
            u64 vp = fma2(s2, U0[i], mul2(c2, V0[i]));
            u64 up = fma2(c2, U0[i], mul2(ns2, V0[i]));
            U0[i] = vp; V0[i] = up;
        }
        float dd = t0 * p0;
        float tmp = nu0 - dd;
        nu0 = nv0 + dd;
        nv0 = tmp;
    }
    {
        u64 c2 = pk2(c1, c1), s2 = pk2(s1, s1), ns2 = pk2(-s1, -s1);
#pragma unroll
        for (int i = 0; i < 4; ++i) {
            u64 vp = fma2(s2, U1[i], mul2(c2, V1[i]));
            u64 up = fma2(c2, U1[i], mul2(ns2, V1[i]));
            U1[i] = vp; V1[i] = up;
        }
        float dd = t1 * p1;
        float tmp = nu1 - dd;
        nu1 = nv1 + dd;
        nv1 = tmp;
    }
}

// ---------------- 128-thread in-place matmuls ----------------
__device__ __forceinline__ void mmip_left(const float* __restrict__ A, float* __restrict__ X,
                                          int gt, int bid) {
    const int r0 = (gt >> 3) << 2;
    const int cc = (gt & 7) << 2;
#pragma unroll
    for (int cb = 0; cb < 2; ++cb) {
        const int c0 = (cb << 5) + cc;
        u64 acc[8];
#pragma unroll
        for (int i = 0; i < 8; ++i) acc[i] = 0ull;
#pragma unroll 4
        for (int k = 0; k < 64; ++k) {
            float a0 = A[r0 * LDB + k],       a1 = A[(r0 + 1) * LDB + k];
            float a2 = A[(r0 + 2) * LDB + k], a3 = A[(r0 + 3) * LDB + k];
            ulonglong2 b = *(const ulonglong2*)&X[k * LDB + c0];
            u64 p;
            p = pk2(a0, a0); acc[0] = fma2(p, b.x, acc[0]); acc[1] = fma2(p, b.y, acc[1]);
            p = pk2(a1, a1); acc[2] = fma2(p, b.x, acc[2]); acc[3] = fma2(p, b.y, acc[3]);
            p = pk2(a2, a2); acc[4] = fma2(p, b.x, acc[4]); acc[5] = fma2(p, b.y, acc[5]);
            p = pk2(a3, a3); acc[6] = fma2(p, b.x, acc[6]); acc[7] = fma2(p, b.y, acc[7]);
        }
        barg(bid);
#pragma unroll
        for (int i = 0; i < 4; ++i)
            *(ulonglong2*)&X[(r0 + i) * LDB + c0] = make_ulonglong2(acc[2 * i], acc[2 * i + 1]);
        barg(bid);
    }
}

__device__ __forceinline__ void mmip_right(float* __restrict__ X, const float* __restrict__ B,
                                           int gt, int bid) {
    const int rr = (gt >> 4) << 2;
    const int c0 = (gt & 15) << 2;
#pragma unroll
    for (int rb = 0; rb < 2; ++rb) {
        const int r0 = (rb << 5) + rr;
        u64 acc[8];
#pragma unroll
        for (int i = 0; i < 8; ++i) acc[i] = 0ull;
#pragma unroll 4
        for (int k = 0; k < 64; ++k) {
            float a0 = X[r0 * LDB + k],       a1 = X[(r0 + 1) * LDB + k];
            float a2 = X[(r0 + 2) * LDB + k], a3 = X[(r0 + 3) * LDB + k];
            ulonglong2 b = *(const ulonglong2*)&B[k * LDB + c0];
            u64 p;
            p = pk2(a0, a0); acc[0] = fma2(p, b.x, acc[0]); acc[1] = fma2(p, b.y, acc[1]);
            p = pk2(a1, a1); acc[2] = fma2(p, b.x, acc[2]); acc[3] = fma2(p, b.y, acc[3]);
            p = pk2(a2, a2); acc[4] = fma2(p, b.x, acc[4]); acc[5] = fma2(p, b.y, acc[5]);
            p = pk2(a3, a3); acc[6] = fma2(p, b.x, acc[6]); acc[7] = fma2(p, b.y, acc[7]);
        }
        barg(bid);
#pragma unroll
        for (int i = 0; i < 4; ++i)
            *(ulonglong2*)&X[(r0 + i) * LDB + c0] = make_ulonglong2(acc[2 * i], acc[2 * i + 1]);
        barg(bid);
    }
}

__device__ __forceinline__ void gram_g(const float* __restrict__ B, const float* __restrict__ fb,
                                       float* __restrict__ out, int gt) {
    const int c0 = (gt & 15) << 2;
    const int rbase = (gt >> 4) << 3;
#pragma unroll
    for (int half = 0; half < 2; ++half) {
        const int r0 = rbase + (half << 2);
        u64 acc[8];
#pragma unroll
        for (int i = 0; i < 8; ++i) acc[i] = 0ull;
#pragma unroll 4
        for (int j = 0; j < 64; ++j) {
            float f = fb[j];
            float4 u = *(const float4*)&B[j * LDB + r0];
            ulonglong2 b = *(const ulonglong2*)&B[j * LDB + c0];
            u64 p;
            p = pk2(f * u.x, f * u.x); acc[0] = fma2(p, b.x, acc[0]); acc[1] = fma2(p, b.y, acc[1]);
            p = pk2(f * u.y, f * u.y); acc[2] = fma2(p, b.x, acc[2]); acc[3] = fma2(p, b.y, acc[3]);
            p = pk2(f * u.z, f * u.z); acc[4] = fma2(p, b.x, acc[4]); acc[5] = fma2(p, b.y, acc[5]);
            p = pk2(f * u.w, f * u.w); acc[6] = fma2(p, b.x, acc[6]); acc[7] = fma2(p, b.y, acc[7]);
        }
#pragma unroll
        for (int i = 0; i < 4; ++i)
            *(ulonglong2*)&out[(r0 + i) * 64 + c0] = make_ulonglong2(acc[2 * i], acc[2 * i + 1]);
    }
}

// ---------------- kernel 0: arithmetic mean ----------------
__global__ __launch_bounds__(256) void mean_partial_kernel(const float* __restrict__ x) {
    const int g = blockIdx.x, tid = threadIdx.x;
    float4 acc[4] = {{0,0,0,0},{0,0,0,0},{0,0,0,0},{0,0,0,0}};
    const float4* xb = (const float4*)(x + (size_t)g * K0_NB * NN);
    for (int b = 0; b < K0_NB; ++b) {
#pragma unroll
        for (int i = 0; i < 4; ++i) {
            float4 v = xb[(size_t)b * 1024 + tid + (i << 8)];
            acc[i].x += v.x; acc[i].y += v.y; acc[i].z += v.z; acc[i].w += v.w;
        }
    }
    float4* pm = (float4*)(g_partial_mean + (size_t)g * NN);
#pragma unroll
    for (int i = 0; i < 4; ++i) pm[tid + (i << 8)] = acc[i];
}

__global__ void reduce_mean_kernel() {
    int j = blockIdx.x * 128 + threadIdx.x;
    float acc = 0.f;
    for (int g = 0; g < K0_BLOCKS; ++g) acc += g_partial_mean[(size_t)g * NN + j];
    g_mean[j] = acc * (1.0f / BATCH);
}

// ---------------- kernel 1: eigh(mean)->s,si ; eigh(G)->gsqrt ----------------
__global__ __launch_bounds__(256) void prep_kernel(const float* __restrict__ G) {
    extern __shared__ float sm[];
    float* A    = sm;
    float* Bsc  = A + 4352;
    float* nbuf = Bsc + 4352;
    const int tid = threadIdx.x;
    load_tile(blockIdx.x == 0 ? g_mean : G, A);
    __syncthreads();
    jacobi_onesided(A, nbuf, SWEEPS_SMALL);
    const int j = tid >> 2, seg = tid & 3;
    float4 v[4];
    float n = colnrm2(A, j, seg, v);
    float lam = fmaxf(sqrtf(n), EPSF);
    float inv_n = 1.0f / n;
    scale_store(Bsc, j, seg, v, sqrtf(lam) * inv_n);
    __syncthreads();
    gram_t4(Bsc, A, blockIdx.x == 0 ? g_s : g_gsqrt, 64);
    if (blockIdx.x == 0) {
        __syncthreads();
        scale_store(Bsc, j, seg, v, rsqrtf(lam) * inv_n);
        __syncthreads();
        gram_t4(Bsc, A, g_si, 64);
    }
}

// ---------------- kernel 2: logm via register-resident odd-even Jacobi ----------------
__global__ __launch_bounds__(256, 3) void batch_log_kernel(const float* __restrict__ x) {
    extern __shared__ float sm[];
    float* T0 = sm;                       // si (shared, read-only)
    const int tid = threadIdx.x;
    const int g = tid >> 7;
    const int gt = tid & 127;
    const int bid = g + 1;
    float* T  = sm + 4352 + g * 4352;
    float* fb = sm + 3 * 4352 + g * 64;

    load_tile(g_si, T0);
    __syncthreads();                      // only block-wide barrier

    const int o  = gt >> 3;               // octet 0..15, positions 4o..4o+3
    const int o0 = (gt & 7) << 2;
    const int o1 = 32 + o0;
    const unsigned omask = 0xFFu << ((tid & 31) & ~7u);
    // exchange buffers inside T (dead during Jacobi)
    float* xcol = T;                      // 16 * 68
    float* ycol = T + 1088;               // 16 * 68
    float* xn   = T + 2176;               // 16
    float* yn   = T + 2192;               // 16

    for (int mi = 0; mi < 2; ++mi) {
        const size_t mat = (size_t)blockIdx.x * 4 + g * 2 + mi;
        const float* xb = x + mat * NN;
        for (int i = gt; i < 1024; i += 128) {
            int r = i >> 4, c4 = (i & 15) << 2;
            *(float4*)&T[r * LDB + c4] = *(const float4*)&xb[(r << 6) + c4];
        }
        barg(bid);
        mmip_left(T0, T, gt, bid);        // T = si @ x
        mmip_right(T, T0, gt, bid);       // T = T @ si

        // load 4 columns into registers
        u64 C[4][4];
        float nrm[4];
#pragma unroll
        for (int c = 0; c < 4; ++c) {
            const float* base = T + (4 * o + c) * LDB;
            ulonglong2 t0 = *(const ulonglong2*)(base + o0);
            ulonglong2 t1 = *(const ulonglong2*)(base + o1);
            C[c][0] = t0.x; C[c][1] = t0.y; C[c][2] = t1.x; C[c][3] = t1.y;
        }
        barg(bid);                        // T reads done; exchange area live

        for (int sw = 0; sw < SWEEPS_BATCH; ++sw) {
            // refresh norms (registers only)
#pragma unroll
            for (int c = 0; c < 4; ++c) {
                u64 d = mul2(C[c][0], C[c][0]);
                d = fma2(C[c][1], C[c][1], d);
                d = fma2(C[c][2], C[c][2], d);
                d = fma2(C[c][3], C[c][3], d);
                float a0, a1; up2(d, a0, a1);
                float n = a0 + a1;
                n += __shfl_xor_sync(omask, n, 1);
                n += __shfl_xor_sync(omask, n, 2);
                n += __shfl_xor_sync(omask, n, 4);
                nrm[c] = n;
            }
            for (int r = 0; r < 32; ++r) {
                // odd round: local pairs (C0,C1), (C2,C3) fused
                rotpair2(C[0], C[1], nrm[0], nrm[1],
                         C[2], C[3], nrm[2], nrm[3], omask);
                // publish C0 for left neighbor's cross pair
                *(ulonglong2*)(xcol + o * 68 + o0) = make_ulonglong2(C[0][0], C[0][1]);
                *(ulonglong2*)(xcol + o * 68 + o1) = make_ulonglong2(C[0][2], C[0][3]);
                if ((gt & 7) == 0) xn[o] = nrm[0];
                // even round internal pair (C1,C2) — overlap with exchange
                rotpair(C[1], C[2], nrm[1], nrm[2], omask);
                barg(bid);
                if (o < 15) {             // cross pair (C3, neighbor C0)
                    u64 D[4];
                    ulonglong2 t0 = *(const ulonglong2*)(xcol + (o + 1) * 68 + o0);
                    ulonglong2 t1 = *(const ulonglong2*)(xcol + (o + 1) * 68 + o1);
                    D[0] = t0.x; D[1] = t0.y; D[2] = t1.x; D[3] = t1.y;
                    float nD = xn[o + 1];
                    rotpair(C[3], D, nrm[3], nD, omask);
                    *(ulonglong2*)(ycol + (o + 1) * 68 + o0) = make_ulonglong2(D[0], D[1]);
                    *(ulonglong2*)(ycol + (o + 1) * 68 + o1) = make_ulonglong2(D[2], D[3]);
                    if ((gt & 7) == 0) yn[o + 1] = nD;
                }
                barg(bid);
                if (o > 0) {              // receive new C0 (position 4o)
                    ulonglong2 t0 = *(const ulonglong2*)(ycol + o * 68 + o0);
                    ulonglong2 t1 = *(const ulonglong2*)(ycol + o * 68 + o1);
                    C[0][0] = t0.x; C[0][1] = t0.y; C[0][2] = t1.x; C[0][3] = t1.y;
                    nrm[0] = yn[o];
                }
            }
        }
        barg(bid);                        // exchange reads done before T overwrite

        // epilogue: exact norms, log factors, store columns back to T
#pragma unroll
        for (int c = 0; c < 4; ++c) {
            u64 d = mul2(C[c][0], C[c][0]);
            d = fma2(C[c][1], C[c][1], d);
            d = fma2(C[c][2], C[c][2], d);
            d = fma2(C[c][3], C[c][3], d);
            float a0, a1; up2(d, a0, a1);
            float n = a0 + a1;
            n += __shfl_xor_sync(omask, n, 1);
            n += __shfl_xor_sync(omask, n, 2);
            n += __shfl_xor_sync(omask, n, 4);
            float* base = T + (4 * o + c) * LDB;
            *(ulonglong2*)(base + o0) = make_ulonglong2(C[c][0], C[c][1]);
            *(ulonglong2*)(base + o1) = make_ulonglong2(C[c][2], C[c][3]);
            if ((gt & 7) == 0) fb[4 * o + c] = logf(fmaxf(sqrtf(n), EPSF)) / n;
        }
        barg(bid);
        gram_g(T, fb, g_partial_t + mat * NN, gt);
        barg(bid);
    }
}

// ---------------- reduce_t: two-stage vectorized ----------------
__global__ __launch_bounds__(256) void reduce_t1_kernel() {
    const int g = blockIdx.x, tid = threadIdx.x;
    float4 acc[4] = {{0,0,0,0},{0,0,0,0},{0,0,0,0},{0,0,0,0}};
    const float4* src = (const float4*)(g_partial_t + (size_t)g * 32 * NN);
    for (int b = 0; b < 32; ++b) {
#pragma unroll
        for (int i = 0; i < 4; ++i) {
            float4 v = src[(size_t)b * 1024 + tid + (i << 8)];
            acc[i].x += v.x; acc[i].y += v.y; acc[i].z += v.z; acc[i].w += v.w;
        }
    }
    float4* pm = (float4*)(g_partial_mean + (size_t)g * NN);
#pragma unroll
    for (int i = 0; i < 4; ++i) pm[tid + (i << 8)] = acc[i];
}

__global__ void reduce_t2_kernel() {
    int j = blockIdx.x * 128 + threadIdx.x;
    float acc = 0.f;
    for (int g = 0; g < RT1_BLOCKS; ++g) acc += g_partial_mean[(size_t)g * NN + j];
    g_tmean[j] = acc * (1.0f / BATCH);
}

// ---------------- kernel 3: expm(tmean) via shifted one-sided, center, csi, W, WT ----------------
__global__ __launch_bounds__(256) void center_kernel() {
    extern __shared__ float sm[];
    float* A    = sm;
    float* T1   = A + 4352;
    float* T2   = T1 + 4352;
    float* fw   = T2 + 4352;
    float* nbuf = fw + 64;
    float* sigp = nbuf + 64;
    const int tid = threadIdx.x;
    const int j = tid >> 2, seg = tid & 3;

    load_tile(g_tmean, A);
    __syncthreads();
    {
        const float4* c = (const float4*)(A + j * LDB + (seg << 4));
        float s = 0.f;
#pragma unroll
        for (int i = 0; i < 4; ++i) {
            float4 v = c[i];
            s += fabsf(v.x) + fabsf(v.y) + fabsf(v.z) + fabsf(v.w);
        }
        s += __shfl_xor_sync(0xffffffffu, s, 1);
        s += __shfl_xor_sync(0xffffffffu, s, 2);
        if (seg == 0) fw[j] = s;
    }
    __syncthreads();
    if (tid == 0) {
        float mx = 0.f;
        for (int i = 0; i < 64; ++i) mx = fmaxf(mx, fw[i]);
        sigp[0] = 1.1f * mx + 1e-2f;
    }
    __syncthreads();
    const float sigma = sigp[0];
    if (tid < 64) A[tid * LDB + tid] += sigma;
    __syncthreads();
    jacobi_onesided(A, nbuf, SWEEPS_SMALL);
    {
        float4 v[4];
        float n = colnrm2(A, j, seg, v);
        float mu = fmaxf(sqrtf(n), EPSF);
        float f = expf(mu - sigma) / n;
        scale_store(T1, j, seg, v, f);
    }
    __syncthreads();
    gram_t4(T1, A, T2, LDB);
    __syncthreads();
    load_tile(g_s, A);
    __syncthreads();
    mm64_t4(A, T2, T1, LDB);  __syncthreads();
    mm64_t4(T1, A, T2, LDB);  __syncthreads();
    jacobi_onesided(T2, nbuf, SWEEPS_SMALL);
    {
        float4 v[4];
        float n = colnrm2(T2, j, seg, v);
        float lam = fmaxf(sqrtf(n), EPSF);
        float f = rsqrtf(lam) / n;
        scale_store(T1, j, seg, v, f);
    }
    __syncthreads();
    gram_t4(T1, T2, A, LDB);
    __syncthreads();
    load_tile(g_gsqrt, T1);
    __syncthreads();
    mm64_t4(T1, A, T2, LDB);
    __syncthreads();
    store_tile(T2, g_W);
    for (int idx = tid; idx < NN; idx += 256) {
        int rr = idx >> 6, cc = idx & 63;
        g_WT[(cc << 6) + rr] = T2[rr * LDB + cc];
    }
}

// ---------------- kernel 4: out_b = W x_b W^T  (4 matrices per block) ----------------
__global__ __launch_bounds__(256) void output_kernel(const float* __restrict__ x,
                                                     float* __restrict__ out) {
    extern __shared__ float sm[];
    float* Ws = sm;
    float* WT = Ws + 4352;
    float* xs = WT + 4352;
    float* P  = xs + 4352;
    load_tile(g_W, Ws);
    load_tile(g_WT, WT);
#pragma unroll
    for (int m = 0; m < 4; ++m) {
        const size_t b = (size_t)blockIdx.x * 4 + m;
        load_tile(x + b * NN, xs);
        __syncthreads();
        mm64_t4(Ws, xs, P, LDB);
        __syncthreads();
        mm64_t4(P, WT, out + b * NN, 64);
        __syncthreads();
    }
}

// ---------------- launcher ----------------
extern "C" void kernel_launch(void* const* d_in, const int* in_sizes, int n_in,
                              void* d_out, int out_size) {
    const float* x;
    const float* G;
    if (in_sizes[0] == NN) { G = (const float*)d_in[0]; x = (const float*)d_in[1]; }
    else                   { x = (const float*)d_in[0]; G = (const float*)d_in[1]; }
    float* out = (float*)d_out;

    constexpr size_t SM_PREP   = (size_t)(2 * 4352 + 64) * 4;
    constexpr size_t SM_BATCH  = (size_t)(3 * 4352 + 128) * 4;
    constexpr size_t SM_CENTER = (size_t)(3 * 4352 + 64 + 64 + 4) * 4;
    constexpr size_t SM_OUT    = (size_t)(4 * 4352) * 4;

    cudaFuncSetAttribute(batch_log_kernel, cudaFuncAttributeMaxDynamicSharedMemorySize, (int)SM_BATCH);
    cudaFuncSetAttribute(center_kernel,    cudaFuncAttributeMaxDynamicSharedMemorySize, (int)SM_CENTER);
    cudaFuncSetAttribute(output_kernel,    cudaFuncAttributeMaxDynamicSharedMemorySize, (int)SM_OUT);

    mean_partial_kernel<<<K0_BLOCKS, 256>>>(x);
    reduce_mean_kernel<<<32, 128>>>();
    prep_kernel<<<2, 256, SM_PREP>>>(G);
    batch_log_kernel<<<K2_BLOCKS, 256, SM_BATCH>>>(x);
    reduce_t1_kernel<<<RT1_BLOCKS, 256>>>();
    reduce_t2_kernel<<<32, 128>>>();
    center_kernel<<<1, 256, SM_CENTER>>>();
    output_kernel<<<BATCH / 4, 256, SM_OUT>>>(x, out);
}